// round 1
// baseline (speedup 1.0000x reference)
#include <cuda_runtime.h>
#include <mma.h>
#include <cstdint>

using namespace nvcuda;

#define NB  8
#define NS  4096
#define ND  1024
#define NA  64
#define NH  8
#define NHD 128
#define NBS (NB*NS)

// ---- scratch (static device globals: alloc-free per harness rules) ----
__device__ float g_hidden[NBS*ND];          // 134 MB
__device__ float g_logits[NBS*NA];
__device__ float g_rw[NBS*NA];
__device__ float g_anchors[NB*NA*ND];
__device__ float g_qkv[NB*NA*3*ND];
__device__ float g_ctx[NB*NA*ND];
__device__ float g_mixed[NB*NA*ND];
__device__ float g_h[NBS*ND];               // 134 MB
__device__ float g_t[134217728];            // 537 MB : FFN intermediate [NBS,4*ND]
__device__ float g_f[NBS*ND];               // 134 MB : token_updates then ffn out
__device__ float g_uvec[ND];
__device__ float g_bvec[ND];

// ============================================================
// Generic tf32 wmma GEMM: C[M,N] = op(A)[M,K] @ B[K,N] (+bias)(+rowscale*coladd)(relu)
// BM=BN=64, BK=32, 128 threads (4 warps, each 32x32).
// TRANS_A: A stored [K,M] row-major -> element(m,k)=A[k*lda+m]
// All problem dims here are multiples of 64/32 -> no bounds checks.
// ============================================================
template<bool TRANS_A, bool RELU>
__global__ void gemm64(const float* __restrict__ Ag, const float* __restrict__ Bg,
                       const float* __restrict__ bias, const float* __restrict__ rowscale,
                       const float* __restrict__ coladd, float* __restrict__ Cg,
                       int M, int N, int K, int lda, int ldb, int ldc,
                       long strideA, long strideB, long strideC)
{
    constexpr int BM = 64, BN = 64, BK = 32;
    __shared__ __align__(32) float sA[BM*36];   // [m][k], ld=36
    __shared__ __align__(32) float sB[BK*68];   // [k][n], ld=68
    __shared__ __align__(32) float sC[64*68];   // epilogue staging

    const float* A = Ag + blockIdx.z * strideA;
    const float* B = Bg + blockIdx.z * strideB;
    float*       C = Cg + blockIdx.z * strideC;

    const int bm = blockIdx.y * BM;
    const int bn = blockIdx.x * BN;
    const int tid  = threadIdx.x;
    const int warp = tid >> 5;
    const int wm = (warp >> 1) * 32;
    const int wn = (warp & 1) * 32;

    wmma::fragment<wmma::accumulator, 16,16,8, float> cf[2][2];
    #pragma unroll
    for (int i = 0; i < 2; i++)
        #pragma unroll
        for (int j = 0; j < 2; j++) wmma::fill_fragment(cf[i][j], 0.0f);

    for (int k0 = 0; k0 < K; k0 += BK) {
        #pragma unroll
        for (int it = 0; it < 16; it++) {
            int idx = tid + it * 128;            // 0..2047 over 64x32
            if (!TRANS_A) {
                int m = idx >> 5, k = idx & 31;
                sA[m*36 + k] = A[(long)(bm + m) * lda + (k0 + k)];
            } else {
                int m = idx & 63, k = idx >> 6;
                sA[m*36 + k] = A[(long)(k0 + k) * lda + (bm + m)];
            }
        }
        #pragma unroll
        for (int it = 0; it < 16; it++) {
            int idx = tid + it * 128;            // 0..2047 over 32x64
            int n = idx & 63, k = idx >> 6;
            sB[k*68 + n] = B[(long)(k0 + k) * ldb + (bn + n)];
        }
        __syncthreads();

        #pragma unroll
        for (int ks = 0; ks < 4; ks++) {
            wmma::fragment<wmma::matrix_a,16,16,8,wmma::precision::tf32,wmma::row_major> af[2];
            wmma::fragment<wmma::matrix_b,16,16,8,wmma::precision::tf32,wmma::row_major> bf[2];
            #pragma unroll
            for (int i = 0; i < 2; i++) {
                wmma::load_matrix_sync(af[i], &sA[(wm + i*16)*36 + ks*8], 36);
                #pragma unroll
                for (int t = 0; t < af[i].num_elements; t++)
                    af[i].x[t] = wmma::__float_to_tf32(af[i].x[t]);
            }
            #pragma unroll
            for (int j = 0; j < 2; j++) {
                wmma::load_matrix_sync(bf[j], &sB[(ks*8)*68 + wn + j*16], 68);
                #pragma unroll
                for (int t = 0; t < bf[j].num_elements; t++)
                    bf[j].x[t] = wmma::__float_to_tf32(bf[j].x[t]);
            }
            #pragma unroll
            for (int i = 0; i < 2; i++)
                #pragma unroll
                for (int j = 0; j < 2; j++)
                    wmma::mma_sync(cf[i][j], af[i], bf[j], cf[i][j]);
        }
        __syncthreads();
    }

    #pragma unroll
    for (int i = 0; i < 2; i++)
        #pragma unroll
        for (int j = 0; j < 2; j++)
            wmma::store_matrix_sync(&sC[(wm + i*16)*68 + wn + j*16], cf[i][j], 68,
                                    wmma::mem_row_major);
    __syncthreads();

    #pragma unroll
    for (int it = 0; it < 32; it++) {
        int idx = tid + it * 128;                // 0..8191 over 64x64
        int r = idx >> 6, c = idx & 63;
        float v = sC[r*68 + c];
        int grow = bm + r, gcol = bn + c;
        if (bias)     v += bias[gcol];
        if (rowscale) v += rowscale[grow] * coladd[gcol];
        if (RELU)     v = fmaxf(v, 0.0f);
        C[(long)grow * ldc + gcol] = v;
    }
}

// ---- fold energy path: u = ep_w @ W1e ; bvec = ep_b @ W1e + rm_b1 ----
__global__ void prep_uv(const float* __restrict__ rm_w1, const float* __restrict__ rm_b1,
                        const float* __restrict__ ep_w, const float* __restrict__ ep_b)
{
    int j = blockIdx.x * blockDim.x + threadIdx.x;
    if (j >= ND) return;
    float u = 0.f, v = 0.f;
    #pragma unroll 8
    for (int a = 0; a < NA; a++) {
        float w = rm_w1[(long)(ND + a) * ND + j];
        u += ep_w[a] * w;
        v += ep_b[a] * w;
    }
    g_uvec[j] = u;
    g_bvec[j] = v + rm_b1[j];
}

// ---- softmax over A=64 (one warp per row) ----
__global__ void softmax64()
{
    int row  = blockIdx.x * 8 + (threadIdx.x >> 5);
    int lane = threadIdx.x & 31;
    const float* lr = g_logits + (long)row * 64;
    float v0 = lr[lane], v1 = lr[lane + 32];
    float m = fmaxf(v0, v1);
    #pragma unroll
    for (int o = 16; o > 0; o >>= 1) m = fmaxf(m, __shfl_xor_sync(0xffffffffu, m, o));
    v0 = expf(v0 - m); v1 = expf(v1 - m);
    float s = v0 + v1;
    #pragma unroll
    for (int o = 16; o > 0; o >>= 1) s += __shfl_xor_sync(0xffffffffu, s, o);
    float inv = 1.0f / s;
    float* rw = g_rw + (long)row * 64;
    rw[lane] = v0 * inv; rw[lane + 32] = v1 * inv;
}

// ---- anchor self-attention: one block per (b,h), A=64, HD=128 ----
__global__ void attn_kernel()
{
    int h = blockIdx.x, b = blockIdx.y;
    const float* base = g_qkv + (long)b * NA * 3 * ND;
    __shared__ float sc[64*64];
    int tid = threadIdx.x;               // 256
    const float scale = 0.08838834764831845f;  // 1/sqrt(128)

    #pragma unroll
    for (int it = 0; it < 16; it++) {
        int idx = tid + it * 256;        // 4096 scores
        int i = idx >> 6, j = idx & 63;
        const float* q = base + (long)i * 3 * ND + h * NHD;
        const float* k = base + (long)j * 3 * ND + ND + h * NHD;
        float acc = 0.f;
        #pragma unroll 8
        for (int d = 0; d < NHD; d++) acc += q[d] * k[d];
        sc[i*64 + j] = acc * scale;
    }
    __syncthreads();

    int warp = tid >> 5, lane = tid & 31;
    for (int r = warp; r < 64; r += 8) {
        float v0 = sc[r*64 + lane], v1 = sc[r*64 + lane + 32];
        float m = fmaxf(v0, v1);
        #pragma unroll
        for (int o = 16; o > 0; o >>= 1) m = fmaxf(m, __shfl_xor_sync(0xffffffffu, m, o));
        v0 = expf(v0 - m); v1 = expf(v1 - m);
        float s = v0 + v1;
        #pragma unroll
        for (int o = 16; o > 0; o >>= 1) s += __shfl_xor_sync(0xffffffffu, s, o);
        float inv = 1.0f / s;
        sc[r*64 + lane] = v0 * inv; sc[r*64 + lane + 32] = v1 * inv;
    }
    __syncthreads();

    #pragma unroll
    for (int it = 0; it < 32; it++) {
        int idx = tid + it * 256;        // 8192 ctx elems
        int i = idx >> 7, d = idx & 127;
        const float* v = base + 2 * ND + h * NHD + d;
        float acc = 0.f;
        #pragma unroll 8
        for (int j = 0; j < 64; j++) acc += sc[i*64 + j] * v[(long)j * 3 * ND];
        g_ctx[((long)b * NA + i) * ND + h * NHD + d] = acc;
    }
}

// ---- block reduction helper ----
__device__ __forceinline__ float blockReduceSum(float v)
{
    __shared__ float sh[9];
    __syncthreads();
    int lane = threadIdx.x & 31, warp = threadIdx.x >> 5;
    #pragma unroll
    for (int o = 16; o > 0; o >>= 1) v += __shfl_xor_sync(0xffffffffu, v, o);
    if (lane == 0) sh[warp] = v;
    __syncthreads();
    if (warp == 0) {
        float t = (lane < 8) ? sh[lane] : 0.f;
        #pragma unroll
        for (int o = 4; o > 0; o >>= 1) t += __shfl_xor_sync(0xffffffffu, t, o);
        if (lane == 0) sh[8] = t;
    }
    __syncthreads();
    return sh[8];
}

// ---- out = LayerNorm(X + Y) * g + b ; one block per row of D=1024 ----
__global__ void add_ln(const float* __restrict__ X, const float* __restrict__ Y,
                       const float* __restrict__ gam, const float* __restrict__ bet,
                       float* __restrict__ out)
{
    long row = blockIdx.x;
    int tid = threadIdx.x;               // 256
    float vals[4];
    float s = 0.f;
    #pragma unroll
    for (int i = 0; i < 4; i++) {
        int d = tid + i * 256;
        float v = X[row * ND + d] + Y[row * ND + d];
        vals[i] = v; s += v;
    }
    float mean = blockReduceSum(s) * (1.0f / ND);
    float vs = 0.f;
    #pragma unroll
    for (int i = 0; i < 4; i++) { float t = vals[i] - mean; vs += t * t; }
    float var = blockReduceSum(vs) * (1.0f / ND);
    float inv = rsqrtf(var + 1e-5f);
    #pragma unroll
    for (int i = 0; i < 4; i++) {
        int d = tid + i * 256;
        out[row * ND + d] = (vals[i] - mean) * inv * gam[d] + bet[d];
    }
}

// ============================================================
extern "C" void kernel_launch(void* const* d_in, const int* in_sizes, int n_in,
                              void* d_out, int out_size)
{
    const float* x     = (const float*)d_in[0];
    const float* efas  = (const float*)d_in[1];
    const float* ep_w  = (const float*)d_in[2];
    const float* ep_b  = (const float*)d_in[3];
    const float* rm_w1 = (const float*)d_in[5];
    const float* rm_b1 = (const float*)d_in[6];
    const float* rm_w2 = (const float*)d_in[7];
    const float* rm_b2 = (const float*)d_in[8];
    const float* in_w  = (const float*)d_in[9];
    const float* in_b  = (const float*)d_in[10];
    const float* ow    = (const float*)d_in[11];
    const float* ob    = (const float*)d_in[12];
    const float* fw1   = (const float*)d_in[13];
    const float* fb1   = (const float*)d_in[14];
    const float* fw2   = (const float*)d_in[15];
    const float* fb2   = (const float*)d_in[16];
    const float* l1g   = (const float*)d_in[17];
    const float* l1b   = (const float*)d_in[18];
    const float* l2g   = (const float*)d_in[19];
    const float* l2b   = (const float*)d_in[20];
    float* out = (float*)d_out;

    float *p_hidden, *p_logits, *p_rw, *p_anchors, *p_qkv, *p_ctx, *p_mixed,
          *p_h, *p_t, *p_f, *p_u, *p_bv;
    cudaGetSymbolAddress((void**)&p_hidden,  g_hidden);
    cudaGetSymbolAddress((void**)&p_logits,  g_logits);
    cudaGetSymbolAddress((void**)&p_rw,      g_rw);
    cudaGetSymbolAddress((void**)&p_anchors, g_anchors);
    cudaGetSymbolAddress((void**)&p_qkv,     g_qkv);
    cudaGetSymbolAddress((void**)&p_ctx,     g_ctx);
    cudaGetSymbolAddress((void**)&p_mixed,   g_mixed);
    cudaGetSymbolAddress((void**)&p_h,       g_h);
    cudaGetSymbolAddress((void**)&p_t,       g_t);
    cudaGetSymbolAddress((void**)&p_f,       g_f);
    cudaGetSymbolAddress((void**)&p_u,       g_uvec);
    cudaGetSymbolAddress((void**)&p_bv,      g_bvec);

    dim3 blk(128);

    // 1) fold energy term
    prep_uv<<<4, 256>>>(rm_w1, rm_b1, ep_w, ep_b);

    // 2) hidden = relu(x@W1x + efas*u + bvec)    [32768,1024]x[1024,1024]
    gemm64<false, true><<<dim3(ND/64, NBS/64), blk>>>(
        x, rm_w1, p_bv, efas, p_u, p_hidden, NBS, ND, ND, ND, ND, ND, 0, 0, 0);

    // 3) logits = hidden @ rm_w2 + rm_b2          [32768,1024]x[1024,64]
    gemm64<false, false><<<dim3(1, NBS/64), blk>>>(
        p_hidden, rm_w2, rm_b2, nullptr, nullptr, p_logits, NBS, NA, ND, ND, NA, NA, 0, 0, 0);

    // 4) routing weights
    softmax64<<<NBS/8, 256>>>();

    // 5) anchors[b] = rw[b]^T @ x[b]              [64,4096]^T x [4096,1024], batched
    gemm64<true, false><<<dim3(ND/64, 1, NB), blk>>>(
        p_rw, x, nullptr, nullptr, nullptr, p_anchors, NA, ND, NS,
        NA, ND, ND, (long)NS*NA, (long)NS*ND, (long)NA*ND);

    // 6) qkv = anchors @ in_w + in_b              [512,1024]x[1024,3072]
    gemm64<false, false><<<dim3(3*ND/64, NB*NA/64), blk>>>(
        p_anchors, in_w, in_b, nullptr, nullptr, p_qkv, NB*NA, 3*ND, ND, ND, 3*ND, 3*ND, 0, 0, 0);

    // 7) anchor attention
    attn_kernel<<<dim3(NH, NB), 256>>>();

    // 8) mixed = ctx @ out_w + out_b              [512,1024]x[1024,1024]
    gemm64<false, false><<<dim3(ND/64, NB*NA/64), blk>>>(
        p_ctx, ow, ob, nullptr, nullptr, p_mixed, NB*NA, ND, ND, ND, ND, ND, 0, 0, 0);

    // 9) token_updates[b] = rw[b] @ mixed[b]      [4096,64]x[64,1024], batched -> g_f
    gemm64<false, false><<<dim3(ND/64, NS/64, NB), blk>>>(
        p_rw, p_mixed, nullptr, nullptr, nullptr, p_f, NS, ND, NA,
        NA, ND, ND, (long)NS*NA, (long)NA*ND, (long)NS*ND);

    // 10) h = LN1(x + token_updates)
    add_ln<<<NBS, 256>>>(x, p_f, l1g, l1b, p_h);

    // 11) t = relu(h @ fw1 + fb1)                 [32768,1024]x[1024,4096]
    gemm64<false, true><<<dim3(4*ND/64, NBS/64), blk>>>(
        p_h, fw1, fb1, nullptr, nullptr, p_t, NBS, 4*ND, ND, ND, 4*ND, 4*ND, 0, 0, 0);

    // 12) f = t @ fw2 + fb2                       [32768,4096]x[4096,1024]
    gemm64<false, false><<<dim3(ND/64, NBS/64), blk>>>(
        p_t, fw2, fb2, nullptr, nullptr, p_f, NBS, ND, 4*ND, 4*ND, ND, ND, 0, 0, 0);

    // 13) out = LN2(h + f)
    add_ln<<<NBS, 256>>>(p_h, p_f, l2g, l2b, out);
}

// round 3
// speedup vs baseline: 1.2552x; 1.2552x over previous
#include <cuda_runtime.h>
#include <mma.h>
#include <cstdint>

using namespace nvcuda;

#define NB  8
#define NS  4096
#define ND  1024
#define NA  64
#define NH  8
#define NHD 128
#define NBS (NB*NS)

// ---- scratch (static device globals: alloc-free per harness rules) ----
__device__ float g_hidden[NBS*ND];
__device__ float g_logits[NBS*NA];
__device__ float g_rw[NBS*NA];
__device__ float g_anchors[NB*NA*ND];
__device__ float g_qkv[NB*NA*3*ND];
__device__ float g_ctx[NB*NA*ND];
__device__ float g_mixed[NB*NA*ND];
__device__ float g_h[NBS*ND];
__device__ float g_t[134217728];            // FFN intermediate [NBS,4*ND]
__device__ float g_f[NBS*ND];
__device__ float g_uvec[ND];
__device__ float g_bvec[ND];

// ---- cp.async helpers ----
__device__ __forceinline__ void cp16(void* smem_dst, const void* gsrc) {
    uint32_t s = (uint32_t)__cvta_generic_to_shared(smem_dst);
    asm volatile("cp.async.cg.shared.global [%0], [%1], 16;\n" :: "r"(s), "l"(gsrc));
}
__device__ __forceinline__ void cp_commit() {
    asm volatile("cp.async.commit_group;\n");
}
template<int N> __device__ __forceinline__ void cp_wait() {
    asm volatile("cp.async.wait_group %0;\n" :: "n"(N));
}

// ============================================================
// gemm128: C[M,N] = A[M,K] @ B[K,N] (+bias)(+rowscale*coladd)(relu)
// BM=BN=128, BK=32. 256 threads (8 warps, 4x2, each 32x64).
// cp.async 2-stage double buffer. tf32 tensor cores with explicit RN
// conversion in fragments (RZ truncation blew the 1e-3 error budget).
// All dims: M%128==0, N%128==0, K%32==0. lda/ldb/ldc %4==0.
// ============================================================
#define G128_AS (128*36)
#define G128_BS (32*132)
#define G128_SMEM ((2*(G128_AS + G128_BS))*4)

template<bool RELU>
__global__ void __launch_bounds__(256, 2)
gemm128(const float* __restrict__ Ag, const float* __restrict__ Bg,
        const float* __restrict__ bias, const float* __restrict__ rowscale,
        const float* __restrict__ coladd, float* __restrict__ Cg,
        int M, int N, int K, int lda, int ldb, int ldc,
        long strideA, long strideB, long strideC)
{
    extern __shared__ float smem[];
    float* sAb[2] = { smem,                     smem + G128_AS + G128_BS };
    float* sBb[2] = { smem + G128_AS,           smem + 2*G128_AS + G128_BS };

    const float* A = Ag + blockIdx.z * strideA;
    const float* B = Bg + blockIdx.z * strideB;
    float*       C = Cg + blockIdx.z * strideC;

    const int bm = blockIdx.y * 128;
    const int bn = blockIdx.x * 128;
    const int tid = threadIdx.x;
    const int warp = tid >> 5;
    const int wm = (warp >> 1) * 32;   // 0,32,64,96
    const int wn = (warp & 1) * 64;    // 0,64

    wmma::fragment<wmma::accumulator, 16,16,8, float> cf[2][4];
    #pragma unroll
    for (int i = 0; i < 2; i++)
        #pragma unroll
        for (int j = 0; j < 4; j++) wmma::fill_fragment(cf[i][j], 0.0f);

    // per-thread load coords (float4 granularity)
    const int am = tid >> 3, akv = tid & 7;     // A: 4 iters of (m += 32)
    const int bk = tid >> 5, bnv = tid & 31;    // B: 4 iters of (k += 8)

    auto issue = [&](int k0, int st) {
        float* sA = sAb[st];
        float* sB = sBb[st];
        #pragma unroll
        for (int i = 0; i < 4; i++) {
            int m = am + i * 32;
            cp16(&sA[m*36 + akv*4], &A[(long)(bm + m) * lda + k0 + akv*4]);
        }
        #pragma unroll
        for (int i = 0; i < 4; i++) {
            int k = bk + i * 8;
            cp16(&sB[k*132 + bnv*4], &B[(long)(k0 + k) * ldb + bn + bnv*4]);
        }
    };

    issue(0, 0); cp_commit();
    const int nIter = K >> 5;

    for (int it = 0; it < nIter; it++) {
        if (it + 1 < nIter) { issue((it+1) << 5, (it+1) & 1); cp_commit(); cp_wait<1>(); }
        else                { cp_wait<0>(); }
        __syncthreads();

        const float* cA = sAb[it & 1];
        const float* cB = sBb[it & 1];
        #pragma unroll
        for (int ks = 0; ks < 4; ks++) {
            wmma::fragment<wmma::matrix_a,16,16,8,wmma::precision::tf32,wmma::row_major> af[2];
            wmma::fragment<wmma::matrix_b,16,16,8,wmma::precision::tf32,wmma::row_major> bf[4];
            #pragma unroll
            for (int i = 0; i < 2; i++) {
                wmma::load_matrix_sync(af[i], &cA[(wm + i*16)*36 + ks*8], 36);
                #pragma unroll
                for (int t = 0; t < af[i].num_elements; t++)
                    af[i].x[t] = wmma::__float_to_tf32(af[i].x[t]);
            }
            #pragma unroll
            for (int j = 0; j < 4; j++) {
                wmma::load_matrix_sync(bf[j], &cB[(ks*8)*132 + wn + j*16], 132);
                #pragma unroll
                for (int t = 0; t < bf[j].num_elements; t++)
                    bf[j].x[t] = wmma::__float_to_tf32(bf[j].x[t]);
            }
            #pragma unroll
            for (int i = 0; i < 2; i++)
                #pragma unroll
                for (int j = 0; j < 4; j++)
                    wmma::mma_sync(cf[i][j], af[i], bf[j], cf[i][j]);
        }
        __syncthreads();
    }

    // epilogue: stage through smem (reuses pipeline buffers)
    float* sC = smem;
    #pragma unroll
    for (int i = 0; i < 2; i++)
        #pragma unroll
        for (int j = 0; j < 4; j++)
            wmma::store_matrix_sync(&sC[(wm + i*16)*132 + wn + j*16], cf[i][j], 132,
                                    wmma::mem_row_major);
    __syncthreads();

    #pragma unroll
    for (int i = 0; i < 16; i++) {
        int idx = tid + i * 256;              // 4096 float4 over 128x128
        int r = idx >> 5, cv = idx & 31;
        float4 v = *(const float4*)&sC[r*132 + cv*4];
        int grow = bm + r, gc = bn + cv*4;
        if (bias) {
            v.x += bias[gc+0]; v.y += bias[gc+1]; v.z += bias[gc+2]; v.w += bias[gc+3];
        }
        if (rowscale) {
            float rs = rowscale[grow];
            v.x += rs * coladd[gc+0]; v.y += rs * coladd[gc+1];
            v.z += rs * coladd[gc+2]; v.w += rs * coladd[gc+3];
        }
        if (RELU) {
            v.x = fmaxf(v.x, 0.f); v.y = fmaxf(v.y, 0.f);
            v.z = fmaxf(v.z, 0.f); v.w = fmaxf(v.w, 0.f);
        }
        *(float4*)&C[(long)grow * ldc + gc] = v;
    }
}

// ============================================================
// gemm64: small/odd shapes (TRANS_A, N=64)
// ============================================================
template<bool TRANS_A, bool RELU>
__global__ void gemm64(const float* __restrict__ Ag, const float* __restrict__ Bg,
                       const float* __restrict__ bias, const float* __restrict__ rowscale,
                       const float* __restrict__ coladd, float* __restrict__ Cg,
                       int M, int N, int K, int lda, int ldb, int ldc,
                       long strideA, long strideB, long strideC)
{
    constexpr int BM = 64, BN = 64, BK = 32;
    __shared__ __align__(32) float sA[BM*36];
    __shared__ __align__(32) float sB[BK*68];
    __shared__ __align__(32) float sC[64*68];

    const float* A = Ag + blockIdx.z * strideA;
    const float* B = Bg + blockIdx.z * strideB;
    float*       C = Cg + blockIdx.z * strideC;

    const int bm = blockIdx.y * BM;
    const int bn = blockIdx.x * BN;
    const int tid  = threadIdx.x;
    const int warp = tid >> 5;
    const int wm = (warp >> 1) * 32;
    const int wn = (warp & 1) * 32;

    wmma::fragment<wmma::accumulator, 16,16,8, float> cf[2][2];
    #pragma unroll
    for (int i = 0; i < 2; i++)
        #pragma unroll
        for (int j = 0; j < 2; j++) wmma::fill_fragment(cf[i][j], 0.0f);

    for (int k0 = 0; k0 < K; k0 += BK) {
        #pragma unroll
        for (int it = 0; it < 16; it++) {
            int idx = tid + it * 128;
            if (!TRANS_A) {
                int m = idx >> 5, k = idx & 31;
                sA[m*36 + k] = A[(long)(bm + m) * lda + (k0 + k)];
            } else {
                int m = idx & 63, k = idx >> 6;
                sA[m*36 + k] = A[(long)(k0 + k) * lda + (bm + m)];
            }
        }
        #pragma unroll
        for (int it = 0; it < 16; it++) {
            int idx = tid + it * 128;
            int n = idx & 63, k = idx >> 6;
            sB[k*68 + n] = B[(long)(k0 + k) * ldb + (bn + n)];
        }
        __syncthreads();

        #pragma unroll
        for (int ks = 0; ks < 4; ks++) {
            wmma::fragment<wmma::matrix_a,16,16,8,wmma::precision::tf32,wmma::row_major> af[2];
            wmma::fragment<wmma::matrix_b,16,16,8,wmma::precision::tf32,wmma::row_major> bf[2];
            #pragma unroll
            for (int i = 0; i < 2; i++) {
                wmma::load_matrix_sync(af[i], &sA[(wm + i*16)*36 + ks*8], 36);
                #pragma unroll
                for (int t = 0; t < af[i].num_elements; t++)
                    af[i].x[t] = wmma::__float_to_tf32(af[i].x[t]);
            }
            #pragma unroll
            for (int j = 0; j < 2; j++) {
                wmma::load_matrix_sync(bf[j], &sB[(ks*8)*68 + wn + j*16], 68);
                #pragma unroll
                for (int t = 0; t < bf[j].num_elements; t++)
                    bf[j].x[t] = wmma::__float_to_tf32(bf[j].x[t]);
            }
            #pragma unroll
            for (int i = 0; i < 2; i++)
                #pragma unroll
                for (int j = 0; j < 2; j++)
                    wmma::mma_sync(cf[i][j], af[i], bf[j], cf[i][j]);
        }
        __syncthreads();
    }

    #pragma unroll
    for (int i = 0; i < 2; i++)
        #pragma unroll
        for (int j = 0; j < 2; j++)
            wmma::store_matrix_sync(&sC[(wm + i*16)*68 + wn + j*16], cf[i][j], 68,
                                    wmma::mem_row_major);
    __syncthreads();

    #pragma unroll
    for (int it = 0; it < 32; it++) {
        int idx = tid + it * 128;
        int r = idx >> 6, c = idx & 63;
        float v = sC[r*68 + c];
        int grow = bm + r, gcol = bn + c;
        if (bias)     v += bias[gcol];
        if (rowscale) v += rowscale[grow] * coladd[gcol];
        if (RELU)     v = fmaxf(v, 0.0f);
        C[(long)grow * ldc + gcol] = v;
    }
}

// ---- fold energy path: u = ep_w @ W1e ; bvec = ep_b @ W1e + rm_b1 ----
__global__ void prep_uv(const float* __restrict__ rm_w1, const float* __restrict__ rm_b1,
                        const float* __restrict__ ep_w, const float* __restrict__ ep_b)
{
    int j = blockIdx.x * blockDim.x + threadIdx.x;
    if (j >= ND) return;
    float u = 0.f, v = 0.f;
    #pragma unroll 8
    for (int a = 0; a < NA; a++) {
        float w = rm_w1[(long)(ND + a) * ND + j];
        u += ep_w[a] * w;
        v += ep_b[a] * w;
    }
    g_uvec[j] = u;
    g_bvec[j] = v + rm_b1[j];
}

// ---- softmax over A=64 (one warp per row) ----
__global__ void softmax64()
{
    int row  = blockIdx.x * 8 + (threadIdx.x >> 5);
    int lane = threadIdx.x & 31;
    const float* lr = g_logits + (long)row * 64;
    float v0 = lr[lane], v1 = lr[lane + 32];
    float m = fmaxf(v0, v1);
    #pragma unroll
    for (int o = 16; o > 0; o >>= 1) m = fmaxf(m, __shfl_xor_sync(0xffffffffu, m, o));
    v0 = expf(v0 - m); v1 = expf(v1 - m);
    float s = v0 + v1;
    #pragma unroll
    for (int o = 16; o > 0; o >>= 1) s += __shfl_xor_sync(0xffffffffu, s, o);
    float inv = 1.0f / s;
    float* rw = g_rw + (long)row * 64;
    rw[lane] = v0 * inv; rw[lane + 32] = v1 * inv;
}

// ---- anchor self-attention: one block per (b,h), A=64, HD=128 ----
__global__ void attn_kernel()
{
    int h = blockIdx.x, b = blockIdx.y;
    const float* base = g_qkv + (long)b * NA * 3 * ND;
    __shared__ float sc[64*64];
    int tid = threadIdx.x;               // 256
    const float scale = 0.08838834764831845f;

    #pragma unroll
    for (int it = 0; it < 16; it++) {
        int idx = tid + it * 256;
        int i = idx >> 6, j = idx & 63;
        const float* q = base + (long)i * 3 * ND + h * NHD;
        const float* k = base + (long)j * 3 * ND + ND + h * NHD;
        float acc = 0.f;
        #pragma unroll 8
        for (int d = 0; d < NHD; d++) acc += q[d] * k[d];
        sc[i*64 + j] = acc * scale;
    }
    __syncthreads();

    int warp = tid >> 5, lane = tid & 31;
    for (int r = warp; r < 64; r += 8) {
        float v0 = sc[r*64 + lane], v1 = sc[r*64 + lane + 32];
        float m = fmaxf(v0, v1);
        #pragma unroll
        for (int o = 16; o > 0; o >>= 1) m = fmaxf(m, __shfl_xor_sync(0xffffffffu, m, o));
        v0 = expf(v0 - m); v1 = expf(v1 - m);
        float s = v0 + v1;
        #pragma unroll
        for (int o = 16; o > 0; o >>= 1) s += __shfl_xor_sync(0xffffffffu, s, o);
        float inv = 1.0f / s;
        sc[r*64 + lane] = v0 * inv; sc[r*64 + lane + 32] = v1 * inv;
    }
    __syncthreads();

    #pragma unroll
    for (int it = 0; it < 32; it++) {
        int idx = tid + it * 256;
        int i = idx >> 7, d = idx & 127;
        const float* v = base + 2 * ND + h * NHD + d;
        float acc = 0.f;
        #pragma unroll 8
        for (int j = 0; j < 64; j++) acc += sc[i*64 + j] * v[(long)j * 3 * ND];
        g_ctx[((long)b * NA + i) * ND + h * NHD + d] = acc;
    }
}

// ---- block reduction helper ----
__device__ __forceinline__ float blockReduceSum(float v)
{
    __shared__ float sh[9];
    __syncthreads();
    int lane = threadIdx.x & 31, warp = threadIdx.x >> 5;
    #pragma unroll
    for (int o = 16; o > 0; o >>= 1) v += __shfl_xor_sync(0xffffffffu, v, o);
    if (lane == 0) sh[warp] = v;
    __syncthreads();
    if (warp == 0) {
        float t = (lane < 8) ? sh[lane] : 0.f;
        #pragma unroll
        for (int o = 4; o > 0; o >>= 1) t += __shfl_xor_sync(0xffffffffu, t, o);
        if (lane == 0) sh[8] = t;
    }
    __syncthreads();
    return sh[8];
}

// ---- out = LayerNorm(X + Y) * g + b ----
__global__ void add_ln(const float* __restrict__ X, const float* __restrict__ Y,
                       const float* __restrict__ gam, const float* __restrict__ bet,
                       float* __restrict__ out)
{
    long row = blockIdx.x;
    int tid = threadIdx.x;               // 256
    float vals[4];
    float s = 0.f;
    #pragma unroll
    for (int i = 0; i < 4; i++) {
        int d = tid + i * 256;
        float v = X[row * ND + d] + Y[row * ND + d];
        vals[i] = v; s += v;
    }
    float mean = blockReduceSum(s) * (1.0f / ND);
    float vs = 0.f;
    #pragma unroll
    for (int i = 0; i < 4; i++) { float t = vals[i] - mean; vs += t * t; }
    float var = blockReduceSum(vs) * (1.0f / ND);
    float inv = rsqrtf(var + 1e-5f);
    #pragma unroll
    for (int i = 0; i < 4; i++) {
        int d = tid + i * 256;
        out[row * ND + d] = (vals[i] - mean) * inv * gam[d] + bet[d];
    }
}

// ============================================================
extern "C" void kernel_launch(void* const* d_in, const int* in_sizes, int n_in,
                              void* d_out, int out_size)
{
    const float* x     = (const float*)d_in[0];
    const float* efas  = (const float*)d_in[1];
    const float* ep_w  = (const float*)d_in[2];
    const float* ep_b  = (const float*)d_in[3];
    const float* rm_w1 = (const float*)d_in[5];
    const float* rm_b1 = (const float*)d_in[6];
    const float* rm_w2 = (const float*)d_in[7];
    const float* rm_b2 = (const float*)d_in[8];
    const float* in_w  = (const float*)d_in[9];
    const float* in_b  = (const float*)d_in[10];
    const float* ow    = (const float*)d_in[11];
    const float* ob    = (const float*)d_in[12];
    const float* fw1   = (const float*)d_in[13];
    const float* fb1   = (const float*)d_in[14];
    const float* fw2   = (const float*)d_in[15];
    const float* fb2   = (const float*)d_in[16];
    const float* l1g   = (const float*)d_in[17];
    const float* l1b   = (const float*)d_in[18];
    const float* l2g   = (const float*)d_in[19];
    const float* l2b   = (const float*)d_in[20];
    float* out = (float*)d_out;

    float *p_hidden, *p_logits, *p_rw, *p_anchors, *p_qkv, *p_ctx, *p_mixed,
          *p_h, *p_t, *p_f, *p_u, *p_bv;
    cudaGetSymbolAddress((void**)&p_hidden,  g_hidden);
    cudaGetSymbolAddress((void**)&p_logits,  g_logits);
    cudaGetSymbolAddress((void**)&p_rw,      g_rw);
    cudaGetSymbolAddress((void**)&p_anchors, g_anchors);
    cudaGetSymbolAddress((void**)&p_qkv,     g_qkv);
    cudaGetSymbolAddress((void**)&p_ctx,     g_ctx);
    cudaGetSymbolAddress((void**)&p_mixed,   g_mixed);
    cudaGetSymbolAddress((void**)&p_h,       g_h);
    cudaGetSymbolAddress((void**)&p_t,       g_t);
    cudaGetSymbolAddress((void**)&p_f,       g_f);
    cudaGetSymbolAddress((void**)&p_u,       g_uvec);
    cudaGetSymbolAddress((void**)&p_bv,      g_bvec);

    static bool attr_set = false;
    if (!attr_set) {
        cudaFuncSetAttribute(gemm128<true>,  cudaFuncAttributeMaxDynamicSharedMemorySize, G128_SMEM);
        cudaFuncSetAttribute(gemm128<false>, cudaFuncAttributeMaxDynamicSharedMemorySize, G128_SMEM);
        attr_set = true;
    }

    dim3 blk64(128), blk128(256);

    // 1) fold energy term
    prep_uv<<<4, 256>>>(rm_w1, rm_b1, ep_w, ep_b);

    // 2) hidden = relu(x@W1x + efas*u + bvec)    [32768,1024]x[1024,1024]
    gemm128<true><<<dim3(ND/128, NBS/128), blk128, G128_SMEM>>>(
        x, rm_w1, p_bv, efas, p_u, p_hidden, NBS, ND, ND, ND, ND, ND, 0, 0, 0);

    // 3) logits = hidden @ rm_w2 + rm_b2          [32768,1024]x[1024,64]
    gemm64<false, false><<<dim3(1, NBS/64), blk64>>>(
        p_hidden, rm_w2, rm_b2, nullptr, nullptr, p_logits, NBS, NA, ND, ND, NA, NA, 0, 0, 0);

    // 4) routing weights
    softmax64<<<NBS/8, 256>>>();

    // 5) anchors[b] = rw[b]^T @ x[b]              batched
    gemm64<true, false><<<dim3(ND/64, 1, NB), blk64>>>(
        p_rw, x, nullptr, nullptr, nullptr, p_anchors, NA, ND, NS,
        NA, ND, ND, (long)NS*NA, (long)NS*ND, (long)NA*ND);

    // 6) qkv = anchors @ in_w + in_b              [512,1024]x[1024,3072]
    gemm128<false><<<dim3(3*ND/128, NB*NA/128), blk128, G128_SMEM>>>(
        p_anchors, in_w, in_b, nullptr, nullptr, p_qkv, NB*NA, 3*ND, ND, ND, 3*ND, 3*ND, 0, 0, 0);

    // 7) anchor attention
    attn_kernel<<<dim3(NH, NB), 256>>>();

    // 8) mixed = ctx @ out_w + out_b              [512,1024]x[1024,1024]
    gemm128<false><<<dim3(ND/128, NB*NA/128), blk128, G128_SMEM>>>(
        p_ctx, ow, ob, nullptr, nullptr, p_mixed, NB*NA, ND, ND, ND, ND, ND, 0, 0, 0);

    // 9) token_updates[b] = rw[b] @ mixed[b]      [4096,64]x[64,1024], batched
    gemm128<false><<<dim3(ND/128, NS/128, NB), blk128, G128_SMEM>>>(
        p_rw, p_mixed, nullptr, nullptr, nullptr, p_f, NS, ND, NA,
        NA, ND, ND, (long)NS*NA, (long)NA*ND, (long)NS*ND);

    // 10) h = LN1(x + token_updates)
    add_ln<<<NBS, 256>>>(x, p_f, l1g, l1b, p_h);

    // 11) t = relu(h @ fw1 + fb1)                 [32768,1024]x[1024,4096]
    gemm128<true><<<dim3(4*ND/128, NBS/128), blk128, G128_SMEM>>>(
        p_h, fw1, fb1, nullptr, nullptr, p_t, NBS, 4*ND, ND, ND, 4*ND, 4*ND, 0, 0, 0);

    // 12) f = t @ fw2 + fb2                       [32768,4096]x[4096,1024]
    gemm128<false><<<dim3(ND/128, NBS/128), blk128, G128_SMEM>>>(
        p_t, fw2, fb2, nullptr, nullptr, p_f, NBS, ND, 4*ND, 4*ND, ND, ND, 0, 0, 0);

    // 13) out = LN2(h + f)
    add_ln<<<NBS, 256>>>(p_h, p_f, l2g, l2b, out);
}

// round 5
// speedup vs baseline: 1.3430x; 1.0700x over previous
#include <cuda_runtime.h>
#include <mma.h>
#include <cstdint>

using namespace nvcuda;

#define NB  8
#define NS  4096
#define ND  1024
#define NA  64
#define NH  8
#define NHD 128
#define NBS (NB*NS)

// ---- scratch (static device globals: alloc-free per harness rules) ----
__device__ float g_hidden[NBS*ND];
__device__ float g_logits[NBS*NA];
__device__ float g_rw[NBS*NA];
__device__ float g_anchors[NB*NA*ND];
__device__ float g_qkv[NB*NA*3*ND];
__device__ float g_ctx[NB*NA*ND];
__device__ float g_mixed[NB*NA*ND];
__device__ float g_h[NBS*ND];
__device__ float g_t[134217728];            // FFN intermediate [NBS,4*ND]
__device__ float g_f[NBS*ND];
__device__ float g_uvec[ND];
__device__ float g_bvec[ND];
// tf32-pre-rounded operands
__device__ float g_xr[NBS*ND];
__device__ float g_w1r[ND*ND];
__device__ float g_w2r[ND*NA];
__device__ float g_inr[ND*3*ND];
__device__ float g_owr[ND*ND];
__device__ float g_f1r[(long)ND*4*ND];
__device__ float g_f2r[(long)4*ND*ND];

// ---- cp.async helpers ----
__device__ __forceinline__ void cp16(void* smem_dst, const void* gsrc) {
    uint32_t s = (uint32_t)__cvta_generic_to_shared(smem_dst);
    asm volatile("cp.async.cg.shared.global [%0], [%1], 16;\n" :: "r"(s), "l"(gsrc));
}
__device__ __forceinline__ void cp_commit() {
    asm volatile("cp.async.commit_group;\n");
}
template<int N> __device__ __forceinline__ void cp_wait() {
    asm volatile("cp.async.wait_group %0;\n" :: "n"(N));
}

__device__ __forceinline__ float rtf(float v) { return wmma::__float_to_tf32(v); }

// ---- elementwise tf32 RN rounding pass ----
__global__ void roundtf(const float4* __restrict__ src, float4* __restrict__ dst, long n4)
{
    long i = (long)blockIdx.x * blockDim.x + threadIdx.x;
    if (i >= n4) return;
    float4 v = src[i];
    v.x = rtf(v.x); v.y = rtf(v.y); v.z = rtf(v.z); v.w = rtf(v.w);
    dst[i] = v;
}

// ============================================================
// gemm128: C[M,N] = A[M,K] @ B[K,N] (+bias)(+rowscale*coladd)(relu)
// Inputs MUST be pre-rounded to tf32 (RN); no in-loop conversion
// (HW RZ truncation is then a no-op). Outputs rounded to tf32.
// BM=BN=128, BK=32. 256 threads (8 warps, 4x2, each 32x64).
// cp.async 2-stage double buffer.
// ============================================================
#define G128_AS (128*36)
#define G128_BS (32*132)
#define G128_SMEM ((2*(G128_AS + G128_BS))*4)

template<bool RELU>
__global__ void __launch_bounds__(256, 2)
gemm128(const float* __restrict__ Ag, const float* __restrict__ Bg,
        const float* __restrict__ bias, const float* __restrict__ rowscale,
        const float* __restrict__ coladd, float* __restrict__ Cg,
        int M, int N, int K, int lda, int ldb, int ldc,
        long strideA, long strideB, long strideC)
{
    extern __shared__ float smemf[];
    float* sAb[2] = { smemf,                     smemf + G128_AS + G128_BS };
    float* sBb[2] = { smemf + G128_AS,           smemf + 2*G128_AS + G128_BS };

    const float* A = Ag + blockIdx.z * strideA;
    const float* B = Bg + blockIdx.z * strideB;
    float*       C = Cg + blockIdx.z * strideC;

    const int bm = blockIdx.y * 128;
    const int bn = blockIdx.x * 128;
    const int tid = threadIdx.x;
    const int warp = tid >> 5;
    const int wm = (warp >> 1) * 32;
    const int wn = (warp & 1) * 64;

    wmma::fragment<wmma::accumulator, 16,16,8, float> cf[2][4];
    #pragma unroll
    for (int i = 0; i < 2; i++)
        #pragma unroll
        for (int j = 0; j < 4; j++) wmma::fill_fragment(cf[i][j], 0.0f);

    const int am = tid >> 3, akv = tid & 7;
    const int bk = tid >> 5, bnv = tid & 31;

    auto issue = [&](int k0, int st) {
        float* sA = sAb[st];
        float* sB = sBb[st];
        #pragma unroll
        for (int i = 0; i < 4; i++) {
            int m = am + i * 32;
            cp16(&sA[m*36 + akv*4], &A[(long)(bm + m) * lda + k0 + akv*4]);
        }
        #pragma unroll
        for (int i = 0; i < 4; i++) {
            int k = bk + i * 8;
            cp16(&sB[k*132 + bnv*4], &B[(long)(k0 + k) * ldb + bn + bnv*4]);
        }
    };

    issue(0, 0); cp_commit();
    const int nIter = K >> 5;

    for (int it = 0; it < nIter; it++) {
        if (it + 1 < nIter) { issue((it+1) << 5, (it+1) & 1); cp_commit(); cp_wait<1>(); }
        else                { cp_wait<0>(); }
        __syncthreads();

        const float* cA = sAb[it & 1];
        const float* cB = sBb[it & 1];
        #pragma unroll
        for (int ks = 0; ks < 4; ks++) {
            wmma::fragment<wmma::matrix_a,16,16,8,wmma::precision::tf32,wmma::row_major> af[2];
            wmma::fragment<wmma::matrix_b,16,16,8,wmma::precision::tf32,wmma::row_major> bf[4];
            #pragma unroll
            for (int i = 0; i < 2; i++)
                wmma::load_matrix_sync(af[i], &cA[(wm + i*16)*36 + ks*8], 36);
            #pragma unroll
            for (int j = 0; j < 4; j++)
                wmma::load_matrix_sync(bf[j], &cB[(ks*8)*132 + wn + j*16], 132);
            #pragma unroll
            for (int i = 0; i < 2; i++)
                #pragma unroll
                for (int j = 0; j < 4; j++)
                    wmma::mma_sync(cf[i][j], af[i], bf[j], cf[i][j]);
        }
        __syncthreads();
    }

    float* sC = smemf;
    #pragma unroll
    for (int i = 0; i < 2; i++)
        #pragma unroll
        for (int j = 0; j < 4; j++)
            wmma::store_matrix_sync(&sC[(wm + i*16)*132 + wn + j*16], cf[i][j], 132,
                                    wmma::mem_row_major);
    __syncthreads();

    #pragma unroll
    for (int i = 0; i < 16; i++) {
        int idx = tid + i * 256;
        int r = idx >> 5, cv = idx & 31;
        float4 v = *(const float4*)&sC[r*132 + cv*4];
        int grow = bm + r, gc = bn + cv*4;
        if (bias) {
            v.x += bias[gc+0]; v.y += bias[gc+1]; v.z += bias[gc+2]; v.w += bias[gc+3];
        }
        if (rowscale) {
            float rs = rowscale[grow];
            v.x += rs * coladd[gc+0]; v.y += rs * coladd[gc+1];
            v.z += rs * coladd[gc+2]; v.w += rs * coladd[gc+3];
        }
        if (RELU) {
            v.x = fmaxf(v.x, 0.f); v.y = fmaxf(v.y, 0.f);
            v.z = fmaxf(v.z, 0.f); v.w = fmaxf(v.w, 0.f);
        }
        v.x = rtf(v.x); v.y = rtf(v.y); v.z = rtf(v.z); v.w = rtf(v.w);
        *(float4*)&C[(long)grow * ldc + gc] = v;
    }
}

// ============================================================
// gemm64: small/odd shapes (TRANS_A, N=64). Pre-rounded inputs.
// ============================================================
template<bool TRANS_A, bool RELU>
__global__ void gemm64(const float* __restrict__ Ag, const float* __restrict__ Bg,
                       const float* __restrict__ bias, const float* __restrict__ rowscale,
                       const float* __restrict__ coladd, float* __restrict__ Cg,
                       int M, int N, int K, int lda, int ldb, int ldc,
                       long strideA, long strideB, long strideC)
{
    constexpr int BM = 64, BN = 64, BK = 32;
    __shared__ __align__(32) float sA[BM*36];
    __shared__ __align__(32) float sB[BK*68];
    __shared__ __align__(32) float sC[64*68];

    const float* A = Ag + blockIdx.z * strideA;
    const float* B = Bg + blockIdx.z * strideB;
    float*       C = Cg + blockIdx.z * strideC;

    const int bm = blockIdx.y * BM;
    const int bn = blockIdx.x * BN;
    const int tid  = threadIdx.x;
    const int warp = tid >> 5;
    const int wm = (warp >> 1) * 32;
    const int wn = (warp & 1) * 32;

    wmma::fragment<wmma::accumulator, 16,16,8, float> cf[2][2];
    #pragma unroll
    for (int i = 0; i < 2; i++)
        #pragma unroll
        for (int j = 0; j < 2; j++) wmma::fill_fragment(cf[i][j], 0.0f);

    for (int k0 = 0; k0 < K; k0 += BK) {
        #pragma unroll
        for (int it = 0; it < 16; it++) {
            int idx = tid + it * 128;
            if (!TRANS_A) {
                int m = idx >> 5, k = idx & 31;
                sA[m*36 + k] = A[(long)(bm + m) * lda + (k0 + k)];
            } else {
                int m = idx & 63, k = idx >> 6;
                sA[m*36 + k] = A[(long)(k0 + k) * lda + (bm + m)];
            }
        }
        #pragma unroll
        for (int it = 0; it < 16; it++) {
            int idx = tid + it * 128;
            int n = idx & 63, k = idx >> 6;
            sB[k*68 + n] = B[(long)(k0 + k) * ldb + (bn + n)];
        }
        __syncthreads();

        #pragma unroll
        for (int ks = 0; ks < 4; ks++) {
            wmma::fragment<wmma::matrix_a,16,16,8,wmma::precision::tf32,wmma::row_major> af[2];
            wmma::fragment<wmma::matrix_b,16,16,8,wmma::precision::tf32,wmma::row_major> bf[2];
            #pragma unroll
            for (int i = 0; i < 2; i++)
                wmma::load_matrix_sync(af[i], &sA[(wm + i*16)*36 + ks*8], 36);
            #pragma unroll
            for (int j = 0; j < 2; j++)
                wmma::load_matrix_sync(bf[j], &sB[(ks*8)*68 + wn + j*16], 68);
            #pragma unroll
            for (int i = 0; i < 2; i++)
                #pragma unroll
                for (int j = 0; j < 2; j++)
                    wmma::mma_sync(cf[i][j], af[i], bf[j], cf[i][j]);
        }
        __syncthreads();
    }

    #pragma unroll
    for (int i = 0; i < 2; i++)
        #pragma unroll
        for (int j = 0; j < 2; j++)
            wmma::store_matrix_sync(&sC[(wm + i*16)*68 + wn + j*16], cf[i][j], 68,
                                    wmma::mem_row_major);
    __syncthreads();

    #pragma unroll
    for (int it = 0; it < 32; it++) {
        int idx = tid + it * 128;
        int r = idx >> 6, c = idx & 63;
        float v = sC[r*68 + c];
        int grow = bm + r, gcol = bn + c;
        if (bias)     v += bias[gcol];
        if (rowscale) v += rowscale[grow] * coladd[gcol];
        if (RELU)     v = fmaxf(v, 0.0f);
        C[(long)grow * ldc + gcol] = rtf(v);
    }
}

// ---- fold energy path ----
__global__ void prep_uv(const float* __restrict__ rm_w1, const float* __restrict__ rm_b1,
                        const float* __restrict__ ep_w, const float* __restrict__ ep_b)
{
    int j = blockIdx.x * blockDim.x + threadIdx.x;
    if (j >= ND) return;
    float u = 0.f, v = 0.f;
    #pragma unroll 8
    for (int a = 0; a < NA; a++) {
        float w = rm_w1[(long)(ND + a) * ND + j];
        u += ep_w[a] * w;
        v += ep_b[a] * w;
    }
    g_uvec[j] = u;
    g_bvec[j] = v + rm_b1[j];
}

// ---- softmax over A=64; outputs tf32-rounded routing weights ----
__global__ void softmax64()
{
    int row  = blockIdx.x * 8 + (threadIdx.x >> 5);
    int lane = threadIdx.x & 31;
    const float* lr = g_logits + (long)row * 64;
    float v0 = lr[lane], v1 = lr[lane + 32];
    float m = fmaxf(v0, v1);
    #pragma unroll
    for (int o = 16; o > 0; o >>= 1) m = fmaxf(m, __shfl_xor_sync(0xffffffffu, m, o));
    v0 = expf(v0 - m); v1 = expf(v1 - m);
    float s = v0 + v1;
    #pragma unroll
    for (int o = 16; o > 0; o >>= 1) s += __shfl_xor_sync(0xffffffffu, s, o);
    float inv = 1.0f / s;
    float* rw = g_rw + (long)row * 64;
    rw[lane] = rtf(v0 * inv); rw[lane + 32] = rtf(v1 * inv);
}

// ---- anchor self-attention; outputs tf32-rounded ctx ----
__global__ void attn_kernel()
{
    int h = blockIdx.x, b = blockIdx.y;
    const float* base = g_qkv + (long)b * NA * 3 * ND;
    __shared__ float sc[64*64];
    int tid = threadIdx.x;
    const float scale = 0.08838834764831845f;

    #pragma unroll
    for (int it = 0; it < 16; it++) {
        int idx = tid + it * 256;
        int i = idx >> 6, j = idx & 63;
        const float* q = base + (long)i * 3 * ND + h * NHD;
        const float* k = base + (long)j * 3 * ND + ND + h * NHD;
        float acc = 0.f;
        #pragma unroll 8
        for (int d = 0; d < NHD; d++) acc += q[d] * k[d];
        sc[i*64 + j] = acc * scale;
    }
    __syncthreads();

    int warp = tid >> 5, lane = tid & 31;
    for (int r = warp; r < 64; r += 8) {
        float v0 = sc[r*64 + lane], v1 = sc[r*64 + lane + 32];
        float m = fmaxf(v0, v1);
        #pragma unroll
        for (int o = 16; o > 0; o >>= 1) m = fmaxf(m, __shfl_xor_sync(0xffffffffu, m, o));
        v0 = expf(v0 - m); v1 = expf(v1 - m);
        float s = v0 + v1;
        #pragma unroll
        for (int o = 16; o > 0; o >>= 1) s += __shfl_xor_sync(0xffffffffu, s, o);
        float inv = 1.0f / s;
        sc[r*64 + lane] = v0 * inv; sc[r*64 + lane + 32] = v1 * inv;
    }
    __syncthreads();

    #pragma unroll
    for (int it = 0; it < 32; it++) {
        int idx = tid + it * 256;
        int i = idx >> 7, d = idx & 127;
        const float* v = base + 2 * ND + h * NHD + d;
        float acc = 0.f;
        #pragma unroll 8
        for (int j = 0; j < 64; j++) acc += sc[i*64 + j] * v[(long)j * 3 * ND];
        g_ctx[((long)b * NA + i) * ND + h * NHD + d] = rtf(acc);
    }
}

__device__ __forceinline__ float blockReduceSum(float v)
{
    __shared__ float sh[9];
    __syncthreads();
    int lane = threadIdx.x & 31, warp = threadIdx.x >> 5;
    #pragma unroll
    for (int o = 16; o > 0; o >>= 1) v += __shfl_xor_sync(0xffffffffu, v, o);
    if (lane == 0) sh[warp] = v;
    __syncthreads();
    if (warp == 0) {
        float t = (lane < 8) ? sh[lane] : 0.f;
        #pragma unroll
        for (int o = 4; o > 0; o >>= 1) t += __shfl_xor_sync(0xffffffffu, t, o);
        if (lane == 0) sh[8] = t;
    }
    __syncthreads();
    return sh[8];
}

// ---- out = LayerNorm(X + Y) * g + b ; round_out: tf32-round the result ----
__global__ void add_ln(const float* __restrict__ X, const float* __restrict__ Y,
                       const float* __restrict__ gam, const float* __restrict__ bet,
                       float* __restrict__ out, int round_out)
{
    long row = blockIdx.x;
    int tid = threadIdx.x;
    float vals[4];
    float s = 0.f;
    #pragma unroll
    for (int i = 0; i < 4; i++) {
        int d = tid + i * 256;
        float v = X[row * ND + d] + Y[row * ND + d];
        vals[i] = v; s += v;
    }
    float mean = blockReduceSum(s) * (1.0f / ND);
    float vs = 0.f;
    #pragma unroll
    for (int i = 0; i < 4; i++) { float t = vals[i] - mean; vs += t * t; }
    float var = blockReduceSum(vs) * (1.0f / ND);
    float inv = rsqrtf(var + 1e-5f);
    #pragma unroll
    for (int i = 0; i < 4; i++) {
        int d = tid + i * 256;
        float o = (vals[i] - mean) * inv * gam[d] + bet[d];
        out[row * ND + d] = round_out ? rtf(o) : o;
    }
}

// ============================================================
extern "C" void kernel_launch(void* const* d_in, const int* in_sizes, int n_in,
                              void* d_out, int out_size)
{
    const float* x     = (const float*)d_in[0];
    const float* efas  = (const float*)d_in[1];
    const float* ep_w  = (const float*)d_in[2];
    const float* ep_b  = (const float*)d_in[3];
    const float* rm_w1 = (const float*)d_in[5];
    const float* rm_b1 = (const float*)d_in[6];
    const float* rm_w2 = (const float*)d_in[7];
    const float* rm_b2 = (const float*)d_in[8];
    const float* in_w  = (const float*)d_in[9];
    const float* in_b  = (const float*)d_in[10];
    const float* ow    = (const float*)d_in[11];
    const float* ob    = (const float*)d_in[12];
    const float* fw1   = (const float*)d_in[13];
    const float* fb1   = (const float*)d_in[14];
    const float* fw2   = (const float*)d_in[15];
    const float* fb2   = (const float*)d_in[16];
    const float* l1g   = (const float*)d_in[17];
    const float* l1b   = (const float*)d_in[18];
    const float* l2g   = (const float*)d_in[19];
    const float* l2b   = (const float*)d_in[20];
    float* out = (float*)d_out;

    float *p_hidden, *p_logits, *p_rw, *p_anchors, *p_qkv, *p_ctx, *p_mixed,
          *p_h, *p_t, *p_f, *p_u, *p_bv;
    float *p_xr, *p_w1r, *p_w2r, *p_inr, *p_owr, *p_f1r, *p_f2r;
    cudaGetSymbolAddress((void**)&p_hidden,  g_hidden);
    cudaGetSymbolAddress((void**)&p_logits,  g_logits);
    cudaGetSymbolAddress((void**)&p_rw,      g_rw);
    cudaGetSymbolAddress((void**)&p_anchors, g_anchors);
    cudaGetSymbolAddress((void**)&p_qkv,     g_qkv);
    cudaGetSymbolAddress((void**)&p_ctx,     g_ctx);
    cudaGetSymbolAddress((void**)&p_mixed,   g_mixed);
    cudaGetSymbolAddress((void**)&p_h,       g_h);
    cudaGetSymbolAddress((void**)&p_t,       g_t);
    cudaGetSymbolAddress((void**)&p_f,       g_f);
    cudaGetSymbolAddress((void**)&p_u,       g_uvec);
    cudaGetSymbolAddress((void**)&p_bv,      g_bvec);
    cudaGetSymbolAddress((void**)&p_xr,      g_xr);
    cudaGetSymbolAddress((void**)&p_w1r,     g_w1r);
    cudaGetSymbolAddress((void**)&p_w2r,     g_w2r);
    cudaGetSymbolAddress((void**)&p_inr,     g_inr);
    cudaGetSymbolAddress((void**)&p_owr,     g_owr);
    cudaGetSymbolAddress((void**)&p_f1r,     g_f1r);
    cudaGetSymbolAddress((void**)&p_f2r,     g_f2r);

    static bool attr_set = false;
    if (!attr_set) {
        cudaFuncSetAttribute(gemm128<true>,  cudaFuncAttributeMaxDynamicSharedMemorySize, G128_SMEM);
        cudaFuncSetAttribute(gemm128<false>, cudaFuncAttributeMaxDynamicSharedMemorySize, G128_SMEM);
        attr_set = true;
    }

    dim3 blk64(128), blk128(256);

    // 0) fold energy term + pre-round all GEMM operands to tf32 (RN)
    prep_uv<<<4, 256>>>(rm_w1, rm_b1, ep_w, ep_b);
    auto rl = [](long n) { return (unsigned)((n/4 + 255) / 256); };
    roundtf<<<rl((long)NBS*ND), 256>>>((const float4*)x,     (float4*)p_xr,  (long)NBS*ND/4);
    roundtf<<<rl((long)ND*ND), 256>>>((const float4*)rm_w1,  (float4*)p_w1r, (long)ND*ND/4);
    roundtf<<<rl((long)ND*NA), 256>>>((const float4*)rm_w2,  (float4*)p_w2r, (long)ND*NA/4);
    roundtf<<<rl((long)ND*3*ND), 256>>>((const float4*)in_w, (float4*)p_inr, (long)ND*3*ND/4);
    roundtf<<<rl((long)ND*ND), 256>>>((const float4*)ow,     (float4*)p_owr, (long)ND*ND/4);
    roundtf<<<rl((long)ND*4*ND), 256>>>((const float4*)fw1,  (float4*)p_f1r, (long)ND*4*ND/4);
    roundtf<<<rl((long)4*ND*ND), 256>>>((const float4*)fw2,  (float4*)p_f2r, (long)4*ND*ND/4);

    // 1) hidden = relu(xr@W1r + efas*u + bvec)    [32768,1024]x[1024,1024]
    gemm128<true><<<dim3(ND/128, NBS/128), blk128, G128_SMEM>>>(
        p_xr, p_w1r, p_bv, efas, p_u, p_hidden, NBS, ND, ND, ND, ND, ND, 0, 0, 0);

    // 2) logits = hidden @ w2r + rm_b2            [32768,1024]x[1024,64]
    gemm64<false, false><<<dim3(1, NBS/64), blk64>>>(
        p_hidden, p_w2r, rm_b2, nullptr, nullptr, p_logits, NBS, NA, ND, ND, NA, NA, 0, 0, 0);

    // 3) routing weights (tf32-rounded)
    softmax64<<<NBS/8, 256>>>();

    // 4) anchors[b] = rw[b]^T @ xr[b]             batched
    gemm64<true, false><<<dim3(ND/64, 1, NB), blk64>>>(
        p_rw, p_xr, nullptr, nullptr, nullptr, p_anchors, NA, ND, NS,
        NA, ND, ND, (long)NS*NA, (long)NS*ND, (long)NA*ND);

    // 5) qkv = anchors @ inr + in_b               [512,1024]x[1024,3072]
    gemm128<false><<<dim3(3*ND/128, NB*NA/128), blk128, G128_SMEM>>>(
        p_anchors, p_inr, in_b, nullptr, nullptr, p_qkv, NB*NA, 3*ND, ND, ND, 3*ND, 3*ND, 0, 0, 0);

    // 6) anchor attention
    attn_kernel<<<dim3(NH, NB), 256>>>();

    // 7) mixed = ctx @ owr + ob                   [512,1024]x[1024,1024]
    gemm128<false><<<dim3(ND/128, NB*NA/128), blk128, G128_SMEM>>>(
        p_ctx, p_owr, ob, nullptr, nullptr, p_mixed, NB*NA, ND, ND, ND, ND, ND, 0, 0, 0);

    // 8) token_updates[b] = rw[b] @ mixed[b]      [4096,64]x[64,1024], batched
    gemm128<false><<<dim3(ND/128, NS/128, NB), blk128, G128_SMEM>>>(
        p_rw, p_mixed, nullptr, nullptr, nullptr, p_f, NS, ND, NA,
        NA, ND, ND, (long)NS*NA, (long)NA*ND, (long)NS*ND);

    // 9) h = LN1(x + token_updates)   (tf32-rounded: feeds ffn1 GEMM)
    add_ln<<<NBS, 256>>>(x, p_f, l1g, l1b, p_h, 1);

    // 10) t = relu(h @ f1r + fb1)                 [32768,1024]x[1024,4096]
    gemm128<true><<<dim3(4*ND/128, NBS/128), blk128, G128_SMEM>>>(
        p_h, p_f1r, fb1, nullptr, nullptr, p_t, NBS, 4*ND, ND, ND, 4*ND, 4*ND, 0, 0, 0);

    // 11) f = t @ f2r + fb2                       [32768,4096]x[4096,1024]
    gemm128<false><<<dim3(ND/128, NBS/128), blk128, G128_SMEM>>>(
        p_t, p_f2r, fb2, nullptr, nullptr, p_f, NBS, ND, 4*ND, 4*ND, ND, ND, 0, 0, 0);

    // 12) out = LN2(h + f)  (full precision)
    add_ln<<<NBS, 256>>>(p_h, p_f, l2g, l2b, out, 0);
}

// round 6
// speedup vs baseline: 1.4863x; 1.1067x over previous
#include <cuda_runtime.h>
#include <mma.h>
#include <cstdint>

using namespace nvcuda;

#define NB  8
#define NS  4096
#define ND  1024
#define NA  64
#define NH  8
#define NHD 128
#define NBS (NB*NS)

// ---- scratch (static device globals: alloc-free per harness rules) ----
__device__ float g_hidden[NBS*ND];
__device__ float g_logits[NBS*NA];
__device__ float g_rw[NBS*NA];
__device__ float g_anchors[NB*NA*ND];
__device__ float g_qkv[NB*NA*3*ND];
__device__ float g_ctx[NB*NA*ND];
__device__ float g_mixed[NB*NA*ND];
__device__ float g_h[NBS*ND];
__device__ float g_t[134217728];            // FFN intermediate [NBS,4*ND]
__device__ float g_f[NBS*ND];
__device__ float g_uvec[ND];
__device__ float g_bvec[ND];
// tf32-pre-rounded operands
__device__ float g_xr[NBS*ND];
__device__ float g_w1r[ND*ND];
__device__ float g_w2r[ND*NA];
__device__ float g_inr[ND*3*ND];
__device__ float g_owr[ND*ND];
__device__ float g_f1r[(long)ND*4*ND];
__device__ float g_f2r[(long)4*ND*ND];

// ---- cp.async helpers ----
__device__ __forceinline__ void cp16(void* smem_dst, const void* gsrc) {
    uint32_t s = (uint32_t)__cvta_generic_to_shared(smem_dst);
    asm volatile("cp.async.cg.shared.global [%0], [%1], 16;\n" :: "r"(s), "l"(gsrc));
}
__device__ __forceinline__ void cp_commit() {
    asm volatile("cp.async.commit_group;\n");
}
template<int N> __device__ __forceinline__ void cp_wait() {
    asm volatile("cp.async.wait_group %0;\n" :: "n"(N));
}

__device__ __forceinline__ float rtf(float v) { return wmma::__float_to_tf32(v); }

// ---- elementwise tf32 RN rounding pass ----
__global__ void roundtf(const float4* __restrict__ src, float4* __restrict__ dst, long n4)
{
    long i = (long)blockIdx.x * blockDim.x + threadIdx.x;
    if (i >= n4) return;
    float4 v = src[i];
    v.x = rtf(v.x); v.y = rtf(v.y); v.z = rtf(v.z); v.w = rtf(v.w);
    dst[i] = v;
}

// ============================================================
// gemm256: C[M,N] = A[M,K] @ B[K,N] (+bias)(+rowscale*coladd)(relu)
// CTA tile 128(M) x 256(N), BK=32. 256 threads, 8 warps (2x4), each 64x64.
// 3-stage cp.async pipeline. Pre-rounded tf32 inputs; no in-loop cvt.
// Fragment loads per MMA = 0.5 (vs 0.75 in gemm128).
// Dims: M%128==0, N%256==0, K%32==0.
// ============================================================
#define G256_A (128*36)
#define G256_B (32*260)
#define G256_STG (G256_A + G256_B)          // floats per stage = 12928
#define G256_SMEM (3*G256_STG*4)            // 155136 bytes

template<bool RELU>
__global__ void __launch_bounds__(256, 1)
gemm256(const float* __restrict__ Ag, const float* __restrict__ Bg,
        const float* __restrict__ bias, const float* __restrict__ rowscale,
        const float* __restrict__ coladd, float* __restrict__ Cg,
        int M, int N, int K, int lda, int ldb, int ldc,
        long strideA, long strideB, long strideC)
{
    extern __shared__ float smemf[];
    const float* A = Ag + blockIdx.z * strideA;
    const float* B = Bg + blockIdx.z * strideB;
    float*       C = Cg + blockIdx.z * strideC;

    const int bm = blockIdx.y * 128;
    const int bn = blockIdx.x * 256;
    const int tid = threadIdx.x;
    const int warp = tid >> 5;
    const int wm = (warp >> 2) * 64;   // 0,64
    const int wn = (warp & 3) * 64;    // 0,64,128,192

    wmma::fragment<wmma::accumulator, 16,16,8, float> cf[4][4];
    #pragma unroll
    for (int i = 0; i < 4; i++)
        #pragma unroll
        for (int j = 0; j < 4; j++) wmma::fill_fragment(cf[i][j], 0.0f);

    const int am  = tid >> 3, akv = tid & 7;    // A: rows am+i*32, col akv*4
    const int bkr = tid >> 6, bnv = tid & 63;   // B: rows bkr+i*4, col bnv*4

    auto issue = [&](int k0, int st) {
        float* sA = smemf + st * G256_STG;
        float* sB = sA + G256_A;
        #pragma unroll
        for (int i = 0; i < 4; i++) {
            int m = am + i * 32;
            cp16(&sA[m*36 + akv*4], &A[(long)(bm + m) * lda + k0 + akv*4]);
        }
        #pragma unroll
        for (int i = 0; i < 8; i++) {
            int k = bkr + i * 4;
            cp16(&sB[k*260 + bnv*4], &B[(long)(k0 + k) * ldb + bn + bnv*4]);
        }
    };

    const int nIter = K >> 5;
    issue(0, 0); cp_commit();
    if (nIter > 1) { issue(32, 1); cp_commit(); }

    for (int it = 0; it < nIter; it++) {
        if (it + 1 < nIter) cp_wait<1>(); else cp_wait<0>();
        __syncthreads();

        int jn = it + 2;
        if (jn < nIter) { issue(jn << 5, jn % 3); cp_commit(); }

        const float* cA = smemf + (it % 3) * G256_STG;
        const float* cB = cA + G256_A;
        #pragma unroll
        for (int ks = 0; ks < 4; ks++) {
            wmma::fragment<wmma::matrix_a,16,16,8,wmma::precision::tf32,wmma::row_major> af[4];
            wmma::fragment<wmma::matrix_b,16,16,8,wmma::precision::tf32,wmma::row_major> bf[4];
            #pragma unroll
            for (int i = 0; i < 4; i++)
                wmma::load_matrix_sync(af[i], &cA[(wm + i*16)*36 + ks*8], 36);
            #pragma unroll
            for (int j = 0; j < 4; j++)
                wmma::load_matrix_sync(bf[j], &cB[(ks*8)*260 + wn + j*16], 260);
            #pragma unroll
            for (int i = 0; i < 4; i++)
                #pragma unroll
                for (int j = 0; j < 4; j++)
                    wmma::mma_sync(cf[i][j], af[i], bf[j], cf[i][j]);
        }
    }

    __syncthreads();
    float* sC = smemf;                       // 128*260 floats <= 3*G256_STG
    #pragma unroll
    for (int i = 0; i < 4; i++)
        #pragma unroll
        for (int j = 0; j < 4; j++)
            wmma::store_matrix_sync(&sC[(wm + i*16)*260 + wn + j*16], cf[i][j], 260,
                                    wmma::mem_row_major);
    __syncthreads();

    #pragma unroll
    for (int i = 0; i < 32; i++) {
        int idx = tid + i * 256;              // 8192 float4 over 128x256
        int r = idx >> 6, cv = idx & 63;
        float4 v = *(const float4*)&sC[r*260 + cv*4];
        int grow = bm + r, gc = bn + cv*4;
        if (bias) {
            v.x += bias[gc+0]; v.y += bias[gc+1]; v.z += bias[gc+2]; v.w += bias[gc+3];
        }
        if (rowscale) {
            float rs = rowscale[grow];
            v.x += rs * coladd[gc+0]; v.y += rs * coladd[gc+1];
            v.z += rs * coladd[gc+2]; v.w += rs * coladd[gc+3];
        }
        if (RELU) {
            v.x = fmaxf(v.x, 0.f); v.y = fmaxf(v.y, 0.f);
            v.z = fmaxf(v.z, 0.f); v.w = fmaxf(v.w, 0.f);
        }
        v.x = rtf(v.x); v.y = rtf(v.y); v.z = rtf(v.z); v.w = rtf(v.w);
        *(float4*)&C[(long)grow * ldc + gc] = v;
    }
}

// ============================================================
// gemm128 (round-5): kept for the M=512 GEMMs (qkv, mixed)
// ============================================================
#define G128_AS (128*36)
#define G128_BS (32*132)
#define G128_SMEM ((2*(G128_AS + G128_BS))*4)

template<bool RELU>
__global__ void __launch_bounds__(256, 2)
gemm128(const float* __restrict__ Ag, const float* __restrict__ Bg,
        const float* __restrict__ bias, const float* __restrict__ rowscale,
        const float* __restrict__ coladd, float* __restrict__ Cg,
        int M, int N, int K, int lda, int ldb, int ldc,
        long strideA, long strideB, long strideC)
{
    extern __shared__ float smemf[];
    float* sAb[2] = { smemf,                     smemf + G128_AS + G128_BS };
    float* sBb[2] = { smemf + G128_AS,           smemf + 2*G128_AS + G128_BS };

    const float* A = Ag + blockIdx.z * strideA;
    const float* B = Bg + blockIdx.z * strideB;
    float*       C = Cg + blockIdx.z * strideC;

    const int bm = blockIdx.y * 128;
    const int bn = blockIdx.x * 128;
    const int tid = threadIdx.x;
    const int warp = tid >> 5;
    const int wm = (warp >> 1) * 32;
    const int wn = (warp & 1) * 64;

    wmma::fragment<wmma::accumulator, 16,16,8, float> cf[2][4];
    #pragma unroll
    for (int i = 0; i < 2; i++)
        #pragma unroll
        for (int j = 0; j < 4; j++) wmma::fill_fragment(cf[i][j], 0.0f);

    const int am = tid >> 3, akv = tid & 7;
    const int bk = tid >> 5, bnv = tid & 31;

    auto issue = [&](int k0, int st) {
        float* sA = sAb[st];
        float* sB = sBb[st];
        #pragma unroll
        for (int i = 0; i < 4; i++) {
            int m = am + i * 32;
            cp16(&sA[m*36 + akv*4], &A[(long)(bm + m) * lda + k0 + akv*4]);
        }
        #pragma unroll
        for (int i = 0; i < 4; i++) {
            int k = bk + i * 8;
            cp16(&sB[k*132 + bnv*4], &B[(long)(k0 + k) * ldb + bn + bnv*4]);
        }
    };

    issue(0, 0); cp_commit();
    const int nIter = K >> 5;

    for (int it = 0; it < nIter; it++) {
        if (it + 1 < nIter) { issue((it+1) << 5, (it+1) & 1); cp_commit(); cp_wait<1>(); }
        else                { cp_wait<0>(); }
        __syncthreads();

        const float* cA = sAb[it & 1];
        const float* cB = sBb[it & 1];
        #pragma unroll
        for (int ks = 0; ks < 4; ks++) {
            wmma::fragment<wmma::matrix_a,16,16,8,wmma::precision::tf32,wmma::row_major> af[2];
            wmma::fragment<wmma::matrix_b,16,16,8,wmma::precision::tf32,wmma::row_major> bf[4];
            #pragma unroll
            for (int i = 0; i < 2; i++)
                wmma::load_matrix_sync(af[i], &cA[(wm + i*16)*36 + ks*8], 36);
            #pragma unroll
            for (int j = 0; j < 4; j++)
                wmma::load_matrix_sync(bf[j], &cB[(ks*8)*132 + wn + j*16], 132);
            #pragma unroll
            for (int i = 0; i < 2; i++)
                #pragma unroll
                for (int j = 0; j < 4; j++)
                    wmma::mma_sync(cf[i][j], af[i], bf[j], cf[i][j]);
        }
        __syncthreads();
    }

    float* sC = smemf;
    #pragma unroll
    for (int i = 0; i < 2; i++)
        #pragma unroll
        for (int j = 0; j < 4; j++)
            wmma::store_matrix_sync(&sC[(wm + i*16)*132 + wn + j*16], cf[i][j], 132,
                                    wmma::mem_row_major);
    __syncthreads();

    #pragma unroll
    for (int i = 0; i < 16; i++) {
        int idx = tid + i * 256;
        int r = idx >> 5, cv = idx & 31;
        float4 v = *(const float4*)&sC[r*132 + cv*4];
        int grow = bm + r, gc = bn + cv*4;
        if (bias) {
            v.x += bias[gc+0]; v.y += bias[gc+1]; v.z += bias[gc+2]; v.w += bias[gc+3];
        }
        if (rowscale) {
            float rs = rowscale[grow];
            v.x += rs * coladd[gc+0]; v.y += rs * coladd[gc+1];
            v.z += rs * coladd[gc+2]; v.w += rs * coladd[gc+3];
        }
        if (RELU) {
            v.x = fmaxf(v.x, 0.f); v.y = fmaxf(v.y, 0.f);
            v.z = fmaxf(v.z, 0.f); v.w = fmaxf(v.w, 0.f);
        }
        v.x = rtf(v.x); v.y = rtf(v.y); v.z = rtf(v.z); v.w = rtf(v.w);
        *(float4*)&C[(long)grow * ldc + gc] = v;
    }
}

// ============================================================
// gemm64: small/odd shapes (TRANS_A, N=64). Pre-rounded inputs.
// ============================================================
template<bool TRANS_A, bool RELU>
__global__ void gemm64(const float* __restrict__ Ag, const float* __restrict__ Bg,
                       const float* __restrict__ bias, const float* __restrict__ rowscale,
                       const float* __restrict__ coladd, float* __restrict__ Cg,
                       int M, int N, int K, int lda, int ldb, int ldc,
                       long strideA, long strideB, long strideC)
{
    constexpr int BM = 64, BN = 64, BK = 32;
    __shared__ __align__(32) float sA[BM*36];
    __shared__ __align__(32) float sB[BK*68];
    __shared__ __align__(32) float sC[64*68];

    const float* A = Ag + blockIdx.z * strideA;
    const float* B = Bg + blockIdx.z * strideB;
    float*       C = Cg + blockIdx.z * strideC;

    const int bm = blockIdx.y * BM;
    const int bn = blockIdx.x * BN;
    const int tid  = threadIdx.x;
    const int warp = tid >> 5;
    const int wm = (warp >> 1) * 32;
    const int wn = (warp & 1) * 32;

    wmma::fragment<wmma::accumulator, 16,16,8, float> cf[2][2];
    #pragma unroll
    for (int i = 0; i < 2; i++)
        #pragma unroll
        for (int j = 0; j < 2; j++) wmma::fill_fragment(cf[i][j], 0.0f);

    for (int k0 = 0; k0 < K; k0 += BK) {
        #pragma unroll
        for (int it = 0; it < 16; it++) {
            int idx = tid + it * 128;
            if (!TRANS_A) {
                int m = idx >> 5, k = idx & 31;
                sA[m*36 + k] = A[(long)(bm + m) * lda + (k0 + k)];
            } else {
                int m = idx & 63, k = idx >> 6;
                sA[m*36 + k] = A[(long)(k0 + k) * lda + (bm + m)];
            }
        }
        #pragma unroll
        for (int it = 0; it < 16; it++) {
            int idx = tid + it * 128;
            int n = idx & 63, k = idx >> 6;
            sB[k*68 + n] = B[(long)(k0 + k) * ldb + (bn + n)];
        }
        __syncthreads();

        #pragma unroll
        for (int ks = 0; ks < 4; ks++) {
            wmma::fragment<wmma::matrix_a,16,16,8,wmma::precision::tf32,wmma::row_major> af[2];
            wmma::fragment<wmma::matrix_b,16,16,8,wmma::precision::tf32,wmma::row_major> bf[2];
            #pragma unroll
            for (int i = 0; i < 2; i++)
                wmma::load_matrix_sync(af[i], &sA[(wm + i*16)*36 + ks*8], 36);
            #pragma unroll
            for (int j = 0; j < 2; j++)
                wmma::load_matrix_sync(bf[j], &sB[(ks*8)*68 + wn + j*16], 68);
            #pragma unroll
            for (int i = 0; i < 2; i++)
                #pragma unroll
                for (int j = 0; j < 2; j++)
                    wmma::mma_sync(cf[i][j], af[i], bf[j], cf[i][j]);
        }
        __syncthreads();
    }

    #pragma unroll
    for (int i = 0; i < 2; i++)
        #pragma unroll
        for (int j = 0; j < 2; j++)
            wmma::store_matrix_sync(&sC[(wm + i*16)*68 + wn + j*16], cf[i][j], 68,
                                    wmma::mem_row_major);
    __syncthreads();

    #pragma unroll
    for (int it = 0; it < 32; it++) {
        int idx = tid + it * 128;
        int r = idx >> 6, c = idx & 63;
        float v = sC[r*68 + c];
        int grow = bm + r, gcol = bn + c;
        if (bias)     v += bias[gcol];
        if (rowscale) v += rowscale[grow] * coladd[gcol];
        if (RELU)     v = fmaxf(v, 0.0f);
        C[(long)grow * ldc + gcol] = rtf(v);
    }
}

// ---- fold energy path ----
__global__ void prep_uv(const float* __restrict__ rm_w1, const float* __restrict__ rm_b1,
                        const float* __restrict__ ep_w, const float* __restrict__ ep_b)
{
    int j = blockIdx.x * blockDim.x + threadIdx.x;
    if (j >= ND) return;
    float u = 0.f, v = 0.f;
    #pragma unroll 8
    for (int a = 0; a < NA; a++) {
        float w = rm_w1[(long)(ND + a) * ND + j];
        u += ep_w[a] * w;
        v += ep_b[a] * w;
    }
    g_uvec[j] = u;
    g_bvec[j] = v + rm_b1[j];
}

// ---- softmax over A=64; outputs tf32-rounded routing weights ----
__global__ void softmax64()
{
    int row  = blockIdx.x * 8 + (threadIdx.x >> 5);
    int lane = threadIdx.x & 31;
    const float* lr = g_logits + (long)row * 64;
    float v0 = lr[lane], v1 = lr[lane + 32];
    float m = fmaxf(v0, v1);
    #pragma unroll
    for (int o = 16; o > 0; o >>= 1) m = fmaxf(m, __shfl_xor_sync(0xffffffffu, m, o));
    v0 = expf(v0 - m); v1 = expf(v1 - m);
    float s = v0 + v1;
    #pragma unroll
    for (int o = 16; o > 0; o >>= 1) s += __shfl_xor_sync(0xffffffffu, s, o);
    float inv = 1.0f / s;
    float* rw = g_rw + (long)row * 64;
    rw[lane] = rtf(v0 * inv); rw[lane + 32] = rtf(v1 * inv);
}

// ---- anchor self-attention; outputs tf32-rounded ctx ----
__global__ void attn_kernel()
{
    int h = blockIdx.x, b = blockIdx.y;
    const float* base = g_qkv + (long)b * NA * 3 * ND;
    __shared__ float sc[64*64];
    int tid = threadIdx.x;
    const float scale = 0.08838834764831845f;

    #pragma unroll
    for (int it = 0; it < 16; it++) {
        int idx = tid + it * 256;
        int i = idx >> 6, j = idx & 63;
        const float* q = base + (long)i * 3 * ND + h * NHD;
        const float* k = base + (long)j * 3 * ND + ND + h * NHD;
        float acc = 0.f;
        #pragma unroll 8
        for (int d = 0; d < NHD; d++) acc += q[d] * k[d];
        sc[i*64 + j] = acc * scale;
    }
    __syncthreads();

    int warp = tid >> 5, lane = tid & 31;
    for (int r = warp; r < 64; r += 8) {
        float v0 = sc[r*64 + lane], v1 = sc[r*64 + lane + 32];
        float m = fmaxf(v0, v1);
        #pragma unroll
        for (int o = 16; o > 0; o >>= 1) m = fmaxf(m, __shfl_xor_sync(0xffffffffu, m, o));
        v0 = expf(v0 - m); v1 = expf(v1 - m);
        float s = v0 + v1;
        #pragma unroll
        for (int o = 16; o > 0; o >>= 1) s += __shfl_xor_sync(0xffffffffu, s, o);
        float inv = 1.0f / s;
        sc[r*64 + lane] = v0 * inv; sc[r*64 + lane + 32] = v1 * inv;
    }
    __syncthreads();

    #pragma unroll
    for (int it = 0; it < 32; it++) {
        int idx = tid + it * 256;
        int i = idx >> 7, d = idx & 127;
        const float* v = base + 2 * ND + h * NHD + d;
        float acc = 0.f;
        #pragma unroll 8
        for (int j = 0; j < 64; j++) acc += sc[i*64 + j] * v[(long)j * 3 * ND];
        g_ctx[((long)b * NA + i) * ND + h * NHD + d] = rtf(acc);
    }
}

__device__ __forceinline__ float blockReduceSum(float v)
{
    __shared__ float sh[9];
    __syncthreads();
    int lane = threadIdx.x & 31, warp = threadIdx.x >> 5;
    #pragma unroll
    for (int o = 16; o > 0; o >>= 1) v += __shfl_xor_sync(0xffffffffu, v, o);
    if (lane == 0) sh[warp] = v;
    __syncthreads();
    if (warp == 0) {
        float t = (lane < 8) ? sh[lane] : 0.f;
        #pragma unroll
        for (int o = 4; o > 0; o >>= 1) t += __shfl_xor_sync(0xffffffffu, t, o);
        if (lane == 0) sh[8] = t;
    }
    __syncthreads();
    return sh[8];
}

// ---- out = LayerNorm(X + Y) * g + b ; round_out: tf32-round result ----
__global__ void add_ln(const float* __restrict__ X, const float* __restrict__ Y,
                       const float* __restrict__ gam, const float* __restrict__ bet,
                       float* __restrict__ out, int round_out)
{
    long row = blockIdx.x;
    int tid = threadIdx.x;
    float vals[4];
    float s = 0.f;
    #pragma unroll
    for (int i = 0; i < 4; i++) {
        int d = tid + i * 256;
        float v = X[row * ND + d] + Y[row * ND + d];
        vals[i] = v; s += v;
    }
    float mean = blockReduceSum(s) * (1.0f / ND);
    float vs = 0.f;
    #pragma unroll
    for (int i = 0; i < 4; i++) { float t = vals[i] - mean; vs += t * t; }
    float var = blockReduceSum(vs) * (1.0f / ND);
    float inv = rsqrtf(var + 1e-5f);
    #pragma unroll
    for (int i = 0; i < 4; i++) {
        int d = tid + i * 256;
        float o = (vals[i] - mean) * inv * gam[d] + bet[d];
        out[row * ND + d] = round_out ? rtf(o) : o;
    }
}

// ============================================================
extern "C" void kernel_launch(void* const* d_in, const int* in_sizes, int n_in,
                              void* d_out, int out_size)
{
    const float* x     = (const float*)d_in[0];
    const float* efas  = (const float*)d_in[1];
    const float* ep_w  = (const float*)d_in[2];
    const float* ep_b  = (const float*)d_in[3];
    const float* rm_w1 = (const float*)d_in[5];
    const float* rm_b1 = (const float*)d_in[6];
    const float* rm_w2 = (const float*)d_in[7];
    const float* rm_b2 = (const float*)d_in[8];
    const float* in_w  = (const float*)d_in[9];
    const float* in_b  = (const float*)d_in[10];
    const float* ow    = (const float*)d_in[11];
    const float* ob    = (const float*)d_in[12];
    const float* fw1   = (const float*)d_in[13];
    const float* fb1   = (const float*)d_in[14];
    const float* fw2   = (const float*)d_in[15];
    const float* fb2   = (const float*)d_in[16];
    const float* l1g   = (const float*)d_in[17];
    const float* l1b   = (const float*)d_in[18];
    const float* l2g   = (const float*)d_in[19];
    const float* l2b   = (const float*)d_in[20];
    float* out = (float*)d_out;

    float *p_hidden, *p_logits, *p_rw, *p_anchors, *p_qkv, *p_ctx, *p_mixed,
          *p_h, *p_t, *p_f, *p_u, *p_bv;
    float *p_xr, *p_w1r, *p_w2r, *p_inr, *p_owr, *p_f1r, *p_f2r;
    cudaGetSymbolAddress((void**)&p_hidden,  g_hidden);
    cudaGetSymbolAddress((void**)&p_logits,  g_logits);
    cudaGetSymbolAddress((void**)&p_rw,      g_rw);
    cudaGetSymbolAddress((void**)&p_anchors, g_anchors);
    cudaGetSymbolAddress((void**)&p_qkv,     g_qkv);
    cudaGetSymbolAddress((void**)&p_ctx,     g_ctx);
    cudaGetSymbolAddress((void**)&p_mixed,   g_mixed);
    cudaGetSymbolAddress((void**)&p_h,       g_h);
    cudaGetSymbolAddress((void**)&p_t,       g_t);
    cudaGetSymbolAddress((void**)&p_f,       g_f);
    cudaGetSymbolAddress((void**)&p_u,       g_uvec);
    cudaGetSymbolAddress((void**)&p_bv,      g_bvec);
    cudaGetSymbolAddress((void**)&p_xr,      g_xr);
    cudaGetSymbolAddress((void**)&p_w1r,     g_w1r);
    cudaGetSymbolAddress((void**)&p_w2r,     g_w2r);
    cudaGetSymbolAddress((void**)&p_inr,     g_inr);
    cudaGetSymbolAddress((void**)&p_owr,     g_owr);
    cudaGetSymbolAddress((void**)&p_f1r,     g_f1r);
    cudaGetSymbolAddress((void**)&p_f2r,     g_f2r);

    static bool attr_set = false;
    if (!attr_set) {
        cudaFuncSetAttribute(gemm128<true>,  cudaFuncAttributeMaxDynamicSharedMemorySize, G128_SMEM);
        cudaFuncSetAttribute(gemm128<false>, cudaFuncAttributeMaxDynamicSharedMemorySize, G128_SMEM);
        cudaFuncSetAttribute(gemm256<true>,  cudaFuncAttributeMaxDynamicSharedMemorySize, G256_SMEM);
        cudaFuncSetAttribute(gemm256<false>, cudaFuncAttributeMaxDynamicSharedMemorySize, G256_SMEM);
        attr_set = true;
    }

    dim3 blk64(128), blk(256);
    auto rl = [](long n) { return (unsigned)((n/4 + 255) / 256); };

    // Launch order chosen so the hidden GEMM is launch index 5 (ncu -s 5 -c 1).
    prep_uv<<<4, 256>>>(rm_w1, rm_b1, ep_w, ep_b);                                     // 0
    roundtf<<<rl((long)NBS*ND), 256>>>((const float4*)x,    (float4*)p_xr,  (long)NBS*ND/4);   // 1
    roundtf<<<rl((long)ND*ND), 256>>>((const float4*)rm_w1, (float4*)p_w1r, (long)ND*ND/4);    // 2
    roundtf<<<rl((long)ND*4*ND), 256>>>((const float4*)fw1, (float4*)p_f1r, (long)ND*4*ND/4);  // 3
    roundtf<<<rl((long)4*ND*ND), 256>>>((const float4*)fw2, (float4*)p_f2r, (long)4*ND*ND/4);  // 4

    // 5) hidden = relu(xr@W1r + efas*u + bvec)    [32768,1024]x[1024,1024]  ← ncu target
    gemm256<true><<<dim3(ND/256, NBS/128), blk, G256_SMEM>>>(
        p_xr, p_w1r, p_bv, efas, p_u, p_hidden, NBS, ND, ND, ND, ND, ND, 0, 0, 0);

    roundtf<<<rl((long)ND*NA), 256>>>((const float4*)rm_w2,  (float4*)p_w2r, (long)ND*NA/4);   // 6
    roundtf<<<rl((long)ND*3*ND), 256>>>((const float4*)in_w, (float4*)p_inr, (long)ND*3*ND/4); // 7
    roundtf<<<rl((long)ND*ND), 256>>>((const float4*)ow,     (float4*)p_owr, (long)ND*ND/4);   // 8

    // logits = hidden @ w2r + rm_b2               [32768,1024]x[1024,64]
    gemm64<false, false><<<dim3(1, NBS/64), blk64>>>(
        p_hidden, p_w2r, rm_b2, nullptr, nullptr, p_logits, NBS, NA, ND, ND, NA, NA, 0, 0, 0);

    softmax64<<<NBS/8, 256>>>();

    // anchors[b] = rw[b]^T @ xr[b]                batched
    gemm64<true, false><<<dim3(ND/64, 1, NB), blk64>>>(
        p_rw, p_xr, nullptr, nullptr, nullptr, p_anchors, NA, ND, NS,
        NA, ND, ND, (long)NS*NA, (long)NS*ND, (long)NA*ND);

    // qkv = anchors @ inr + in_b                  [512,1024]x[1024,3072]
    gemm128<false><<<dim3(3*ND/128, NB*NA/128), blk, G128_SMEM>>>(
        p_anchors, p_inr, in_b, nullptr, nullptr, p_qkv, NB*NA, 3*ND, ND, ND, 3*ND, 3*ND, 0, 0, 0);

    attn_kernel<<<dim3(NH, NB), 256>>>();

    // mixed = ctx @ owr + ob                      [512,1024]x[1024,1024]
    gemm128<false><<<dim3(ND/128, NB*NA/128), blk, G128_SMEM>>>(
        p_ctx, p_owr, ob, nullptr, nullptr, p_mixed, NB*NA, ND, ND, ND, ND, ND, 0, 0, 0);

    // token_updates[b] = rw[b] @ mixed[b]         [4096,64]x[64,1024], batched
    gemm256<false><<<dim3(ND/256, NS/128, NB), blk, G256_SMEM>>>(
        p_rw, p_mixed, nullptr, nullptr, nullptr, p_f, NS, ND, NA,
        NA, ND, ND, (long)NS*NA, (long)NA*ND, (long)NS*ND);

    // h = LN1(x + token_updates)  (tf32-rounded: feeds ffn1 GEMM)
    add_ln<<<NBS, 256>>>(x, p_f, l1g, l1b, p_h, 1);

    // t = relu(h @ f1r + fb1)                     [32768,1024]x[1024,4096]
    gemm256<true><<<dim3(4*ND/256, NBS/128), blk, G256_SMEM>>>(
        p_h, p_f1r, fb1, nullptr, nullptr, p_t, NBS, 4*ND, ND, ND, 4*ND, 4*ND, 0, 0, 0);

    // f = t @ f2r + fb2                           [32768,4096]x[4096,1024]
    gemm256<false><<<dim3(ND/256, NBS/128), blk, G256_SMEM>>>(
        p_t, p_f2r, fb2, nullptr, nullptr, p_f, NBS, ND, 4*ND, 4*ND, ND, ND, 0, 0, 0);

    // out = LN2(h + f)  (full precision)
    add_ln<<<NBS, 256>>>(p_h, p_f, l2g, l2b, out, 0);
}

// round 7
// speedup vs baseline: 1.5010x; 1.0098x over previous
#include <cuda_runtime.h>
#include <mma.h>
#include <cstdint>

using namespace nvcuda;

#define NB  8
#define NS  4096
#define ND  1024
#define NA  64
#define NH  8
#define NHD 128
#define NBS (NB*NS)

// ---- scratch (static device globals: alloc-free per harness rules) ----
__device__ float g_hidden[NBS*ND];
__device__ float g_logits[NBS*NA];
__device__ float g_rw[NBS*NA];
__device__ float g_anchors[NB*NA*ND];
__device__ float g_qkv[NB*NA*3*ND];
__device__ float g_ctx[NB*NA*ND];
__device__ float g_mixed[NB*NA*ND];
__device__ float g_h[NBS*ND];
__device__ float g_t[134217728];            // FFN intermediate [NBS,4*ND]
__device__ float g_f[NBS*ND];
__device__ float g_uvec[ND];
__device__ float g_bvec[ND];
// tf32-pre-rounded operands
__device__ float g_xr[NBS*ND];
__device__ float g_w1r[ND*ND];
__device__ float g_w2r[ND*NA];
__device__ float g_inr[ND*3*ND];
__device__ float g_owr[ND*ND];
__device__ float g_f1r[(long)ND*4*ND];
__device__ float g_f2r[(long)4*ND*ND];

// ---- cp.async helpers ----
__device__ __forceinline__ void cp16(void* smem_dst, const void* gsrc) {
    uint32_t s = (uint32_t)__cvta_generic_to_shared(smem_dst);
    asm volatile("cp.async.cg.shared.global [%0], [%1], 16;\n" :: "r"(s), "l"(gsrc));
}
__device__ __forceinline__ void cp_commit() {
    asm volatile("cp.async.commit_group;\n");
}
template<int N> __device__ __forceinline__ void cp_wait() {
    asm volatile("cp.async.wait_group %0;\n" :: "n"(N));
}

__device__ __forceinline__ float rtf(float v) { return wmma::__float_to_tf32(v); }

// ---- elementwise tf32 RN rounding pass ----
__global__ void roundtf(const float4* __restrict__ src, float4* __restrict__ dst, long n4)
{
    long i = (long)blockIdx.x * blockDim.x + threadIdx.x;
    if (i >= n4) return;
    float4 v = src[i];
    v.x = rtf(v.x); v.y = rtf(v.y); v.z = rtf(v.z); v.w = rtf(v.w);
    dst[i] = v;
}

// ============================================================
// gemm_v2: C[M,N] = A[M,K] @ B[K,N] (+bias)(+rowscale*coladd)(relu)
// CTA tile 128x128, 128 threads = 4 warps (2x2), each 64x64.
// BK=32, 3-stage cp.async pipeline, 106KB smem -> 2 CTAs/SM.
// Pre-rounded tf32 inputs; no in-loop cvt.
// Dims: M%128==0, N%128==0, K%32==0, lda/ldb/ldc %4==0.
// ============================================================
#define V2_A (128*36)
#define V2_B (32*132)
#define V2_STG (V2_A + V2_B)          // 8832 floats per stage
#define V2_SMEM (3*V2_STG*4)          // 105984 bytes

template<bool RELU>
__global__ void __launch_bounds__(128, 2)
gemm_v2(const float* __restrict__ Ag, const float* __restrict__ Bg,
        const float* __restrict__ bias, const float* __restrict__ rowscale,
        const float* __restrict__ coladd, float* __restrict__ Cg,
        int M, int N, int K, int lda, int ldb, int ldc,
        long strideA, long strideB, long strideC)
{
    extern __shared__ float smemf[];
    const float* A = Ag + blockIdx.z * strideA;
    const float* B = Bg + blockIdx.z * strideB;
    float*       C = Cg + blockIdx.z * strideC;

    const int bm = blockIdx.y * 128;
    const int bn = blockIdx.x * 128;
    const int tid = threadIdx.x;
    const int warp = tid >> 5;
    const int wm = (warp >> 1) * 64;   // 0,64
    const int wn = (warp & 1) * 64;    // 0,64

    wmma::fragment<wmma::accumulator, 16,16,8, float> cf[4][4];
    #pragma unroll
    for (int i = 0; i < 4; i++)
        #pragma unroll
        for (int j = 0; j < 4; j++) wmma::fill_fragment(cf[i][j], 0.0f);

    // load mapping (float4 granularity, 128 threads)
    const int ar = tid >> 3, ac = tid & 7;     // A: 8 iters rows ar+i*16
    const int br = tid >> 5, bc = tid & 31;    // B: 8 iters rows br+i*4

    auto issue = [&](int k0, int st) {
        float* sA = smemf + st * V2_STG;
        float* sB = sA + V2_A;
        #pragma unroll
        for (int i = 0; i < 8; i++) {
            int m = ar + i * 16;
            cp16(&sA[m*36 + ac*4], &A[(long)(bm + m) * lda + k0 + ac*4]);
        }
        #pragma unroll
        for (int i = 0; i < 8; i++) {
            int k = br + i * 4;
            cp16(&sB[k*132 + bc*4], &B[(long)(k0 + k) * ldb + bn + bc*4]);
        }
    };

    const int nIter = K >> 5;
    issue(0, 0); cp_commit();
    if (nIter > 1) { issue(32, 1); cp_commit(); }

    for (int it = 0; it < nIter; it++) {
        if (it + 1 < nIter) cp_wait<1>(); else cp_wait<0>();
        __syncthreads();

        int jn = it + 2;
        if (jn < nIter) { issue(jn << 5, jn % 3); cp_commit(); }

        const float* cA = smemf + (it % 3) * V2_STG;
        const float* cB = cA + V2_A;
        #pragma unroll
        for (int ks = 0; ks < 4; ks++) {
            wmma::fragment<wmma::matrix_a,16,16,8,wmma::precision::tf32,wmma::row_major> af[4];
            wmma::fragment<wmma::matrix_b,16,16,8,wmma::precision::tf32,wmma::row_major> bf[4];
            #pragma unroll
            for (int i = 0; i < 4; i++)
                wmma::load_matrix_sync(af[i], &cA[(wm + i*16)*36 + ks*8], 36);
            #pragma unroll
            for (int j = 0; j < 4; j++)
                wmma::load_matrix_sync(bf[j], &cB[(ks*8)*132 + wn + j*16], 132);
            #pragma unroll
            for (int i = 0; i < 4; i++)
                #pragma unroll
                for (int j = 0; j < 4; j++)
                    wmma::mma_sync(cf[i][j], af[i], bf[j], cf[i][j]);
        }
    }

    __syncthreads();
    float* sC = smemf;                       // 128*132*4 = 67.6KB <= 106KB
    #pragma unroll
    for (int i = 0; i < 4; i++)
        #pragma unroll
        for (int j = 0; j < 4; j++)
            wmma::store_matrix_sync(&sC[(wm + i*16)*132 + wn + j*16], cf[i][j], 132,
                                    wmma::mem_row_major);
    __syncthreads();

    #pragma unroll
    for (int i = 0; i < 32; i++) {
        int idx = tid + i * 128;              // 4096 float4 over 128x128
        int r = idx >> 5, cv = idx & 31;
        float4 v = *(const float4*)&sC[r*132 + cv*4];
        int grow = bm + r, gc = bn + cv*4;
        if (bias) {
            v.x += bias[gc+0]; v.y += bias[gc+1]; v.z += bias[gc+2]; v.w += bias[gc+3];
        }
        if (rowscale) {
            float rs = rowscale[grow];
            v.x += rs * coladd[gc+0]; v.y += rs * coladd[gc+1];
            v.z += rs * coladd[gc+2]; v.w += rs * coladd[gc+3];
        }
        if (RELU) {
            v.x = fmaxf(v.x, 0.f); v.y = fmaxf(v.y, 0.f);
            v.z = fmaxf(v.z, 0.f); v.w = fmaxf(v.w, 0.f);
        }
        v.x = rtf(v.x); v.y = rtf(v.y); v.z = rtf(v.z); v.w = rtf(v.w);
        *(float4*)&C[(long)grow * ldc + gc] = v;
    }
}

// ============================================================
// gemm64: small/odd shapes (TRANS_A, N=64). Pre-rounded inputs.
// ============================================================
template<bool TRANS_A, bool RELU>
__global__ void gemm64(const float* __restrict__ Ag, const float* __restrict__ Bg,
                       const float* __restrict__ bias, const float* __restrict__ rowscale,
                       const float* __restrict__ coladd, float* __restrict__ Cg,
                       int M, int N, int K, int lda, int ldb, int ldc,
                       long strideA, long strideB, long strideC)
{
    constexpr int BM = 64, BN = 64, BK = 32;
    __shared__ __align__(32) float sA[BM*36];
    __shared__ __align__(32) float sB[BK*68];
    __shared__ __align__(32) float sC[64*68];

    const float* A = Ag + blockIdx.z * strideA;
    const float* B = Bg + blockIdx.z * strideB;
    float*       C = Cg + blockIdx.z * strideC;

    const int bm = blockIdx.y * BM;
    const int bn = blockIdx.x * BN;
    const int tid  = threadIdx.x;
    const int warp = tid >> 5;
    const int wm = (warp >> 1) * 32;
    const int wn = (warp & 1) * 32;

    wmma::fragment<wmma::accumulator, 16,16,8, float> cf[2][2];
    #pragma unroll
    for (int i = 0; i < 2; i++)
        #pragma unroll
        for (int j = 0; j < 2; j++) wmma::fill_fragment(cf[i][j], 0.0f);

    for (int k0 = 0; k0 < K; k0 += BK) {
        #pragma unroll
        for (int it = 0; it < 16; it++) {
            int idx = tid + it * 128;
            if (!TRANS_A) {
                int m = idx >> 5, k = idx & 31;
                sA[m*36 + k] = A[(long)(bm + m) * lda + (k0 + k)];
            } else {
                int m = idx & 63, k = idx >> 6;
                sA[m*36 + k] = A[(long)(k0 + k) * lda + (bm + m)];
            }
        }
        #pragma unroll
        for (int it = 0; it < 16; it++) {
            int idx = tid + it * 128;
            int n = idx & 63, k = idx >> 6;
            sB[k*68 + n] = B[(long)(k0 + k) * ldb + (bn + n)];
        }
        __syncthreads();

        #pragma unroll
        for (int ks = 0; ks < 4; ks++) {
            wmma::fragment<wmma::matrix_a,16,16,8,wmma::precision::tf32,wmma::row_major> af[2];
            wmma::fragment<wmma::matrix_b,16,16,8,wmma::precision::tf32,wmma::row_major> bf[2];
            #pragma unroll
            for (int i = 0; i < 2; i++)
                wmma::load_matrix_sync(af[i], &sA[(wm + i*16)*36 + ks*8], 36);
            #pragma unroll
            for (int j = 0; j < 2; j++)
                wmma::load_matrix_sync(bf[j], &sB[(ks*8)*68 + wn + j*16], 68);
            #pragma unroll
            for (int i = 0; i < 2; i++)
                #pragma unroll
                for (int j = 0; j < 2; j++)
                    wmma::mma_sync(cf[i][j], af[i], bf[j], cf[i][j]);
        }
        __syncthreads();
    }

    #pragma unroll
    for (int i = 0; i < 2; i++)
        #pragma unroll
        for (int j = 0; j < 2; j++)
            wmma::store_matrix_sync(&sC[(wm + i*16)*68 + wn + j*16], cf[i][j], 68,
                                    wmma::mem_row_major);
    __syncthreads();

    #pragma unroll
    for (int it = 0; it < 32; it++) {
        int idx = tid + it * 128;
        int r = idx >> 6, c = idx & 63;
        float v = sC[r*68 + c];
        int grow = bm + r, gcol = bn + c;
        if (bias)     v += bias[gcol];
        if (rowscale) v += rowscale[grow] * coladd[gcol];
        if (RELU)     v = fmaxf(v, 0.0f);
        C[(long)grow * ldc + gcol] = rtf(v);
    }
}

// ---- fold energy path ----
__global__ void prep_uv(const float* __restrict__ rm_w1, const float* __restrict__ rm_b1,
                        const float* __restrict__ ep_w, const float* __restrict__ ep_b)
{
    int j = blockIdx.x * blockDim.x + threadIdx.x;
    if (j >= ND) return;
    float u = 0.f, v = 0.f;
    #pragma unroll 8
    for (int a = 0; a < NA; a++) {
        float w = rm_w1[(long)(ND + a) * ND + j];
        u += ep_w[a] * w;
        v += ep_b[a] * w;
    }
    g_uvec[j] = u;
    g_bvec[j] = v + rm_b1[j];
}

// ---- softmax over A=64; outputs tf32-rounded routing weights ----
__global__ void softmax64()
{
    int row  = blockIdx.x * 8 + (threadIdx.x >> 5);
    int lane = threadIdx.x & 31;
    const float* lr = g_logits + (long)row * 64;
    float v0 = lr[lane], v1 = lr[lane + 32];
    float m = fmaxf(v0, v1);
    #pragma unroll
    for (int o = 16; o > 0; o >>= 1) m = fmaxf(m, __shfl_xor_sync(0xffffffffu, m, o));
    v0 = expf(v0 - m); v1 = expf(v1 - m);
    float s = v0 + v1;
    #pragma unroll
    for (int o = 16; o > 0; o >>= 1) s += __shfl_xor_sync(0xffffffffu, s, o);
    float inv = 1.0f / s;
    float* rw = g_rw + (long)row * 64;
    rw[lane] = rtf(v0 * inv); rw[lane + 32] = rtf(v1 * inv);
}

// ---- anchor self-attention; outputs tf32-rounded ctx ----
__global__ void attn_kernel()
{
    int h = blockIdx.x, b = blockIdx.y;
    const float* base = g_qkv + (long)b * NA * 3 * ND;
    __shared__ float sc[64*64];
    int tid = threadIdx.x;
    const float scale = 0.08838834764831845f;

    #pragma unroll
    for (int it = 0; it < 16; it++) {
        int idx = tid + it * 256;
        int i = idx >> 6, j = idx & 63;
        const float* q = base + (long)i * 3 * ND + h * NHD;
        const float* k = base + (long)j * 3 * ND + ND + h * NHD;
        float acc = 0.f;
        #pragma unroll 8
        for (int d = 0; d < NHD; d++) acc += q[d] * k[d];
        sc[i*64 + j] = acc * scale;
    }
    __syncthreads();

    int warp = tid >> 5, lane = tid & 31;
    for (int r = warp; r < 64; r += 8) {
        float v0 = sc[r*64 + lane], v1 = sc[r*64 + lane + 32];
        float m = fmaxf(v0, v1);
        #pragma unroll
        for (int o = 16; o > 0; o >>= 1) m = fmaxf(m, __shfl_xor_sync(0xffffffffu, m, o));
        v0 = expf(v0 - m); v1 = expf(v1 - m);
        float s = v0 + v1;
        #pragma unroll
        for (int o = 16; o > 0; o >>= 1) s += __shfl_xor_sync(0xffffffffu, s, o);
        float inv = 1.0f / s;
        sc[r*64 + lane] = v0 * inv; sc[r*64 + lane + 32] = v1 * inv;
    }
    __syncthreads();

    #pragma unroll
    for (int it = 0; it < 32; it++) {
        int idx = tid + it * 256;
        int i = idx >> 7, d = idx & 127;
        const float* v = base + 2 * ND + h * NHD + d;
        float acc = 0.f;
        #pragma unroll 8
        for (int j = 0; j < 64; j++) acc += sc[i*64 + j] * v[(long)j * 3 * ND];
        g_ctx[((long)b * NA + i) * ND + h * NHD + d] = rtf(acc);
    }
}

__device__ __forceinline__ float blockReduceSum(float v)
{
    __shared__ float sh[9];
    __syncthreads();
    int lane = threadIdx.x & 31, warp = threadIdx.x >> 5;
    #pragma unroll
    for (int o = 16; o > 0; o >>= 1) v += __shfl_xor_sync(0xffffffffu, v, o);
    if (lane == 0) sh[warp] = v;
    __syncthreads();
    if (warp == 0) {
        float t = (lane < 8) ? sh[lane] : 0.f;
        #pragma unroll
        for (int o = 4; o > 0; o >>= 1) t += __shfl_xor_sync(0xffffffffu, t, o);
        if (lane == 0) sh[8] = t;
    }
    __syncthreads();
    return sh[8];
}

// ---- out = LayerNorm(X + Y) * g + b ; round_out: tf32-round result ----
__global__ void add_ln(const float* __restrict__ X, const float* __restrict__ Y,
                       const float* __restrict__ gam, const float* __restrict__ bet,
                       float* __restrict__ out, int round_out)
{
    long row = blockIdx.x;
    int tid = threadIdx.x;
    float vals[4];
    float s = 0.f;
    #pragma unroll
    for (int i = 0; i < 4; i++) {
        int d = tid + i * 256;
        float v = X[row * ND + d] + Y[row * ND + d];
        vals[i] = v; s += v;
    }
    float mean = blockReduceSum(s) * (1.0f / ND);
    float vs = 0.f;
    #pragma unroll
    for (int i = 0; i < 4; i++) { float t = vals[i] - mean; vs += t * t; }
    float var = blockReduceSum(vs) * (1.0f / ND);
    float inv = rsqrtf(var + 1e-5f);
    #pragma unroll
    for (int i = 0; i < 4; i++) {
        int d = tid + i * 256;
        float o = (vals[i] - mean) * inv * gam[d] + bet[d];
        out[row * ND + d] = round_out ? rtf(o) : o;
    }
}

// ============================================================
extern "C" void kernel_launch(void* const* d_in, const int* in_sizes, int n_in,
                              void* d_out, int out_size)
{
    const float* x     = (const float*)d_in[0];
    const float* efas  = (const float*)d_in[1];
    const float* ep_w  = (const float*)d_in[2];
    const float* ep_b  = (const float*)d_in[3];
    const float* rm_w1 = (const float*)d_in[5];
    const float* rm_b1 = (const float*)d_in[6];
    const float* rm_w2 = (const float*)d_in[7];
    const float* rm_b2 = (const float*)d_in[8];
    const float* in_w  = (const float*)d_in[9];
    const float* in_b  = (const float*)d_in[10];
    const float* ow    = (const float*)d_in[11];
    const float* ob    = (const float*)d_in[12];
    const float* fw1   = (const float*)d_in[13];
    const float* fb1   = (const float*)d_in[14];
    const float* fw2   = (const float*)d_in[15];
    const float* fb2   = (const float*)d_in[16];
    const float* l1g   = (const float*)d_in[17];
    const float* l1b   = (const float*)d_in[18];
    const float* l2g   = (const float*)d_in[19];
    const float* l2b   = (const float*)d_in[20];
    float* out = (float*)d_out;

    float *p_hidden, *p_logits, *p_rw, *p_anchors, *p_qkv, *p_ctx, *p_mixed,
          *p_h, *p_t, *p_f, *p_u, *p_bv;
    float *p_xr, *p_w1r, *p_w2r, *p_inr, *p_owr, *p_f1r, *p_f2r;
    cudaGetSymbolAddress((void**)&p_hidden,  g_hidden);
    cudaGetSymbolAddress((void**)&p_logits,  g_logits);
    cudaGetSymbolAddress((void**)&p_rw,      g_rw);
    cudaGetSymbolAddress((void**)&p_anchors, g_anchors);
    cudaGetSymbolAddress((void**)&p_qkv,     g_qkv);
    cudaGetSymbolAddress((void**)&p_ctx,     g_ctx);
    cudaGetSymbolAddress((void**)&p_mixed,   g_mixed);
    cudaGetSymbolAddress((void**)&p_h,       g_h);
    cudaGetSymbolAddress((void**)&p_t,       g_t);
    cudaGetSymbolAddress((void**)&p_f,       g_f);
    cudaGetSymbolAddress((void**)&p_u,       g_uvec);
    cudaGetSymbolAddress((void**)&p_bv,      g_bvec);
    cudaGetSymbolAddress((void**)&p_xr,      g_xr);
    cudaGetSymbolAddress((void**)&p_w1r,     g_w1r);
    cudaGetSymbolAddress((void**)&p_w2r,     g_w2r);
    cudaGetSymbolAddress((void**)&p_inr,     g_inr);
    cudaGetSymbolAddress((void**)&p_owr,     g_owr);
    cudaGetSymbolAddress((void**)&p_f1r,     g_f1r);
    cudaGetSymbolAddress((void**)&p_f2r,     g_f2r);

    static bool attr_set = false;
    if (!attr_set) {
        cudaFuncSetAttribute(gemm_v2<true>,  cudaFuncAttributeMaxDynamicSharedMemorySize, V2_SMEM);
        cudaFuncSetAttribute(gemm_v2<false>, cudaFuncAttributeMaxDynamicSharedMemorySize, V2_SMEM);
        attr_set = true;
    }

    dim3 blk64(128), blk128(128);
    auto rl = [](long n) { return (unsigned)((n/4 + 255) / 256); };

    // Launch order: hidden GEMM at index 3 (ncu empirically profiles idx 3).
    prep_uv<<<4, 256>>>(rm_w1, rm_b1, ep_w, ep_b);                                             // 0
    roundtf<<<rl((long)NBS*ND), 256>>>((const float4*)x,    (float4*)p_xr,  (long)NBS*ND/4);   // 1
    roundtf<<<rl((long)ND*ND), 256>>>((const float4*)rm_w1, (float4*)p_w1r, (long)ND*ND/4);    // 2

    // 3) hidden = relu(xr@W1r + efas*u + bvec)    [32768,1024]x[1024,1024]  ← ncu target
    gemm_v2<true><<<dim3(ND/128, NBS/128), blk128, V2_SMEM>>>(
        p_xr, p_w1r, p_bv, efas, p_u, p_hidden, NBS, ND, ND, ND, ND, ND, 0, 0, 0);

    roundtf<<<rl((long)ND*NA), 256>>>((const float4*)rm_w2,  (float4*)p_w2r, (long)ND*NA/4);   // 4
    roundtf<<<rl((long)ND*3*ND), 256>>>((const float4*)in_w, (float4*)p_inr, (long)ND*3*ND/4); // 5
    roundtf<<<rl((long)ND*ND), 256>>>((const float4*)ow,     (float4*)p_owr, (long)ND*ND/4);   // 6
    roundtf<<<rl((long)ND*4*ND), 256>>>((const float4*)fw1,  (float4*)p_f1r, (long)ND*4*ND/4); // 7
    roundtf<<<rl((long)4*ND*ND), 256>>>((const float4*)fw2,  (float4*)p_f2r, (long)4*ND*ND/4); // 8

    // logits = hidden @ w2r + rm_b2               [32768,1024]x[1024,64]
    gemm64<false, false><<<dim3(1, NBS/64), blk64>>>(
        p_hidden, p_w2r, rm_b2, nullptr, nullptr, p_logits, NBS, NA, ND, ND, NA, NA, 0, 0, 0);

    softmax64<<<NBS/8, 256>>>();

    // anchors[b] = rw[b]^T @ xr[b]                batched
    gemm64<true, false><<<dim3(ND/64, 1, NB), blk64>>>(
        p_rw, p_xr, nullptr, nullptr, nullptr, p_anchors, NA, ND, NS,
        NA, ND, ND, (long)NS*NA, (long)NS*ND, (long)NA*ND);

    // qkv = anchors @ inr + in_b                  [512,1024]x[1024,3072]
    gemm_v2<false><<<dim3(3*ND/128, NB*NA/128), blk128, V2_SMEM>>>(
        p_anchors, p_inr, in_b, nullptr, nullptr, p_qkv, NB*NA, 3*ND, ND, ND, 3*ND, 3*ND, 0, 0, 0);

    attn_kernel<<<dim3(NH, NB), 256>>>();

    // mixed = ctx @ owr + ob                      [512,1024]x[1024,1024]
    gemm_v2<false><<<dim3(ND/128, NB*NA/128), blk128, V2_SMEM>>>(
        p_ctx, p_owr, ob, nullptr, nullptr, p_mixed, NB*NA, ND, ND, ND, ND, ND, 0, 0, 0);

    // token_updates[b] = rw[b] @ mixed[b]         [4096,64]x[64,1024], batched
    gemm_v2<false><<<dim3(ND/128, NS/128, NB), blk128, V2_SMEM>>>(
        p_rw, p_mixed, nullptr, nullptr, nullptr, p_f, NS, ND, NA,
        NA, ND, ND, (long)NS*NA, (long)NA*ND, (long)NS*ND);

    // h = LN1(x + token_updates)  (tf32-rounded: feeds ffn1 GEMM)
    add_ln<<<NBS, 256>>>(x, p_f, l1g, l1b, p_h, 1);

    // t = relu(h @ f1r + fb1)                     [32768,1024]x[1024,4096]
    gemm_v2<true><<<dim3(4*ND/128, NBS/128), blk128, V2_SMEM>>>(
        p_h, p_f1r, fb1, nullptr, nullptr, p_t, NBS, 4*ND, ND, ND, 4*ND, 4*ND, 0, 0, 0);

    // f = t @ f2r + fb2                           [32768,4096]x[4096,1024]
    gemm_v2<false><<<dim3(ND/128, NBS/128), blk128, V2_SMEM>>>(
        p_t, p_f2r, fb2, nullptr, nullptr, p_f, NBS, ND, 4*ND, 4*ND, ND, ND, 0, 0, 0);

    // out = LN2(h + f)  (full precision)
    add_ln<<<NBS, 256>>>(p_h, p_f, l2g, l2b, out, 0);
}